// round 2
// baseline (speedup 1.0000x reference)
#include <cuda_runtime.h>

#define NNODES 4096
#define NEDGES 32768
#define NSC 48
#define NVC 16
#define NEF 128
#define WNUM 4096
#define BN_EPS 1e-5f
#define INV_SQRT3 0.57735026918962576f
#define ALPHA 0.125f

// ---------------- static device scratch ----------------
__device__ float g_H[NEDGES * NEF];     // H = relu(edge_attr @ W1 + b1), [e][kk]
__device__ float g_W2p[WNUM * NEF];     // fc_w2 transposed: [j][kk]
__device__ float g_accum[NNODES * 96];  // node_attr + segment_sum(msg)
__device__ float g_mean[NSC];
__device__ float g_rs[NSC];
__device__ float g_rsv[NVC];
__device__ int g_src[NEDGES];
__device__ int g_dst[NEDGES];
__device__ int g_mode;

// ---------------- edge_index dtype detection + conversion ----------------
__global__ void k_detect_idx(const int* __restrict__ raw) {
    __shared__ int flag;
    int t = threadIdx.x;
    if (t == 0) flag = 0;
    __syncthreads();
    for (int i = t; i < 2048; i += 256) {
        if (raw[2 * i + 1] != 0) flag = 1;
    }
    __syncthreads();
    if (t == 0) g_mode = flag;
}

__global__ void k_convert_idx(const int* __restrict__ raw) {
    int e = blockIdx.x * 256 + threadIdx.x;
    if (e >= NEDGES) return;
    if (g_mode) {
        g_src[e] = raw[e];
        g_dst[e] = raw[NEDGES + e];
    } else {
        g_src[e] = raw[2 * e];
        g_dst[e] = raw[2 * (NEDGES + e)];
    }
}

// ---------------- W2 transpose: [kk][j] -> [j][kk] ----------------
__global__ void k_transpose_w2(const float* __restrict__ w2) {
    __shared__ float tile[32][33];
    int j0 = blockIdx.x * 32;
    int k0 = blockIdx.y * 32;
    int tx = threadIdx.x, ty = threadIdx.y;
#pragma unroll
    for (int r = ty; r < 32; r += 8)
        tile[r][tx] = w2[(size_t)(k0 + r) * WNUM + j0 + tx];
    __syncthreads();
#pragma unroll
    for (int r = ty; r < 32; r += 8)
        g_W2p[(size_t)(j0 + r) * NEF + k0 + tx] = tile[tx][r];
}

// ---------------- Stage A: H = relu(edge_attr @ W1 + b1) ----------------
__global__ __launch_bounds__(256) void k_stage_a(const float* __restrict__ ea,
                                                 const float* __restrict__ w1,
                                                 const float* __restrict__ b1) {
    __shared__ float As[32][65];
    __shared__ float Ws[32][128];
    int t = threadIdx.x;
    int tx = t & 31, ty = t >> 5;
    int e0 = blockIdx.x * 64;
    float acc[8][4];
#pragma unroll
    for (int i = 0; i < 8; ++i)
#pragma unroll
        for (int j = 0; j < 4; ++j) acc[i][j] = 0.f;

    for (int k0 = 0; k0 < NEF; k0 += 32) {
        for (int idx = t; idx < 64 * 32; idx += 256) {
            int e = idx >> 5, kk = idx & 31;
            As[kk][e] = ea[(size_t)(e0 + e) * NEF + k0 + kk];
        }
        for (int idx = t; idx < 32 * 128; idx += 256) {
            int kk = idx >> 7, cc = idx & 127;
            Ws[kk][cc] = w1[(size_t)(k0 + kk) * NEF + cc];
        }
        __syncthreads();
#pragma unroll 8
        for (int kk = 0; kk < 32; ++kk) {
            float4 b = *reinterpret_cast<const float4*>(&Ws[kk][tx * 4]);
#pragma unroll
            for (int i = 0; i < 8; ++i) {
                float a = As[kk][ty * 8 + i];
                acc[i][0] = fmaf(a, b.x, acc[i][0]);
                acc[i][1] = fmaf(a, b.y, acc[i][1]);
                acc[i][2] = fmaf(a, b.z, acc[i][2]);
                acc[i][3] = fmaf(a, b.w, acc[i][3]);
            }
        }
        __syncthreads();
    }
    float4 bias = *reinterpret_cast<const float4*>(&b1[tx * 4]);
#pragma unroll
    for (int i = 0; i < 8; ++i) {
        float4 o;
        o.x = fmaxf(acc[i][0] + bias.x, 0.f);
        o.y = fmaxf(acc[i][1] + bias.y, 0.f);
        o.z = fmaxf(acc[i][2] + bias.z, 0.f);
        o.w = fmaxf(acc[i][3] + bias.w, 0.f);
        *reinterpret_cast<float4*>(&g_H[(size_t)(e0 + ty * 8 + i) * NEF + tx * 4]) = o;
    }
}

// ---------------- accumulator init with residual ----------------
__global__ void k_init_accum(const float* __restrict__ na) {
    int idx = blockIdx.x * 256 + threadIdx.x;
    if (idx < NNODES * 96) g_accum[idx] = na[idx];
}

// ---------------- Stage B ----------------
struct SmemB {
    float Hs[NEF][65];     // [kk][e] padded
    float coefT[64][64];   // [i][e]
    float xssT[48][64];    // [i][e]
    float xvsT[48][64];    // [3*i+m][e]
    float svs[64][3];
    float sss[64];
    int dsts[64];
    int srcs[64];
};

__device__ __forceinline__ float dlrelu(float x) {
    return (fabsf(x) <= 10.f) ? x : 0.01f * x;
}

// 8 W2 rows (compile-time stride RS4 in float4 units) dotted against 2 H columns.
template <int RS4>
__device__ __forceinline__ void dot8x2(const float4* __restrict__ wb,
                                       const float* __restrict__ hs,
                                       int el0, float c0[8], float c1[8]) {
#pragma unroll
    for (int ti = 0; ti < 8; ++ti) { c0[ti] = 0.f; c1[ti] = 0.f; }
#pragma unroll 2
    for (int kkc = 0; kkc < 32; ++kkc) {
        float h00 = hs[(4 * kkc + 0) * 65 + el0];
        float h01 = hs[(4 * kkc + 1) * 65 + el0];
        float h02 = hs[(4 * kkc + 2) * 65 + el0];
        float h03 = hs[(4 * kkc + 3) * 65 + el0];
        float h10 = hs[(4 * kkc + 0) * 65 + el0 + 32];
        float h11 = hs[(4 * kkc + 1) * 65 + el0 + 32];
        float h12 = hs[(4 * kkc + 2) * 65 + el0 + 32];
        float h13 = hs[(4 * kkc + 3) * 65 + el0 + 32];
#pragma unroll
        for (int ti = 0; ti < 8; ++ti) {
            float4 w = __ldg(wb + ti * RS4 + kkc);
            c0[ti] = fmaf(h00, w.x, c0[ti]);
            c0[ti] = fmaf(h01, w.y, c0[ti]);
            c0[ti] = fmaf(h02, w.z, c0[ti]);
            c0[ti] = fmaf(h03, w.w, c0[ti]);
            c1[ti] = fmaf(h10, w.x, c1[ti]);
            c1[ti] = fmaf(h11, w.y, c1[ti]);
            c1[ti] = fmaf(h12, w.z, c1[ti]);
            c1[ti] = fmaf(h13, w.w, c1[ti]);
        }
    }
}

extern __shared__ char smem_raw[];

__global__ __launch_bounds__(256, 2) void k_stage_b(const float* __restrict__ na,
                                                    const float* __restrict__ sh,
                                                    const float* __restrict__ b2) {
    SmemB& sm = *reinterpret_cast<SmemB*>(smem_raw);
    int t = threadIdx.x;
    int e0 = blockIdx.x * 64;

    if (t < 64) {
        int e = e0 + t;
        sm.srcs[t] = g_src[e];
        sm.dsts[t] = g_dst[e];
        float4 shv = __ldg(reinterpret_cast<const float4*>(sh) + e);
        sm.sss[t] = shv.x;
        sm.svs[t][0] = shv.y;
        sm.svs[t][1] = shv.z;
        sm.svs[t][2] = shv.w;
    }
    __syncthreads();
    // gather node_attr[src] (transposed layouts)
    for (int idx = t; idx < 64 * 96; idx += 256) {
        int e = idx / 96, c = idx % 96;
        float v = na[(size_t)sm.srcs[e] * 96 + c];
        if (c < 48) sm.xssT[c][e] = v;
        else sm.xvsT[c - 48][e] = v;
    }
    // H tile
    for (int idx = t; idx < 64 * NEF; idx += 256) {
        int e = idx >> 7, kk = idx & 127;
        sm.Hs[kk][e] = g_H[(size_t)(e0 + e) * NEF + kk];
    }
    __syncthreads();
    // scalar-path coefficients
    for (int idx = t; idx < 64 * 64; idx += 256) {
        int e = idx >> 6, i = idx & 63;
        float v;
        if (i < 48) {
            v = sm.xssT[i][e] * sm.sss[e];
        } else {
            int i2 = i - 48;
            v = INV_SQRT3 * (sm.xvsT[3 * i2 + 0][e] * sm.svs[e][0]
                           + sm.xvsT[3 * i2 + 1][e] * sm.svs[e][1]
                           + sm.xvsT[3 * i2 + 2][e] * sm.svs[e][2]);
        }
        sm.coefT[i][e] = v;
    }
    __syncthreads();

    int el0 = t & 31;          // lane: first edge; second is el0+32
    int kg = t >> 5;           // warp id 0..7: k residue
    const float* hs = &sm.Hs[0][0];
    float* arow0 = g_accum + (size_t)sm.dsts[el0] * 96;
    float* arow1 = g_accum + (size_t)sm.dsts[el0 + 32] * 96;

    // ---- scalar outputs: k = kg + 8u ----
#pragma unroll 1
    for (int u = 0; u < 6; ++u) {
        int k = kg + 8 * u;
        float acc0 = 0.f, acc1 = 0.f;
#pragma unroll 1
        for (int i0 = 0; i0 < 64; i0 += 8) {
            float c0[8], c1[8];
            const float4* wb = reinterpret_cast<const float4*>(
                g_W2p + (size_t)(i0 * 48 + k) * NEF);
            dot8x2<48 * 32>(wb, hs, el0, c0, c1);
#pragma unroll
            for (int ti = 0; ti < 8; ++ti) {
                float b = __ldg(b2 + (i0 + ti) * 48 + k);
                float cf0 = sm.coefT[i0 + ti][el0];
                float cf1 = sm.coefT[i0 + ti][el0 + 32];
                acc0 = fmaf(cf0, dlrelu(c0[ti] + b), acc0);
                acc1 = fmaf(cf1, dlrelu(c1[ti] + b), acc1);
            }
        }
        atomicAdd(arow0 + k, ALPHA * acc0);
        atomicAdd(arow1 + k, ALPHA * acc1);
    }

    // ---- vector outputs: k = kg + 8u, u in {0,1} ----
#pragma unroll 1
    for (int u = 0; u < 2; ++u) {
        int k = kg + 8 * u;
        float t1_0 = 0.f, t1_1 = 0.f;
        float tv0_0 = 0.f, tv1_0 = 0.f, tv2_0 = 0.f;
        float tv0_1 = 0.f, tv1_1 = 0.f, tv2_1 = 0.f;
#pragma unroll 1
        for (int i0 = 0; i0 < 48; i0 += 8) {  // w_sv block
            float c0[8], c1[8];
            const float4* wb = reinterpret_cast<const float4*>(
                g_W2p + (size_t)(3072 + i0 * 16 + k) * NEF);
            dot8x2<16 * 32>(wb, hs, el0, c0, c1);
#pragma unroll
            for (int ti = 0; ti < 8; ++ti) {
                float b = __ldg(b2 + 3072 + (i0 + ti) * 16 + k);
                float xs0 = sm.xssT[i0 + ti][el0];
                float xs1 = sm.xssT[i0 + ti][el0 + 32];
                t1_0 = fmaf(xs0, dlrelu(c0[ti] + b), t1_0);
                t1_1 = fmaf(xs1, dlrelu(c1[ti] + b), t1_1);
            }
        }
#pragma unroll 1
        for (int i0 = 0; i0 < 16; i0 += 8) {  // w_vv block
            float c0[8], c1[8];
            const float4* wb = reinterpret_cast<const float4*>(
                g_W2p + (size_t)(3840 + i0 * 16 + k) * NEF);
            dot8x2<16 * 32>(wb, hs, el0, c0, c1);
#pragma unroll
            for (int ti = 0; ti < 8; ++ti) {
                int i = i0 + ti;
                float b = __ldg(b2 + 3840 + i * 16 + k);
                float w0 = dlrelu(c0[ti] + b);
                float w1 = dlrelu(c1[ti] + b);
                tv0_0 = fmaf(sm.xvsT[3 * i + 0][el0], w0, tv0_0);
                tv1_0 = fmaf(sm.xvsT[3 * i + 1][el0], w0, tv1_0);
                tv2_0 = fmaf(sm.xvsT[3 * i + 2][el0], w0, tv2_0);
                tv0_1 = fmaf(sm.xvsT[3 * i + 0][el0 + 32], w1, tv0_1);
                tv1_1 = fmaf(sm.xvsT[3 * i + 1][el0 + 32], w1, tv1_1);
                tv2_1 = fmaf(sm.xvsT[3 * i + 2][el0 + 32], w1, tv2_1);
            }
        }
        float ss0 = sm.sss[el0], ss1 = sm.sss[el0 + 32];
        atomicAdd(arow0 + 48 + 3 * k + 0, ALPHA * fmaf(t1_0, sm.svs[el0][0], ss0 * tv0_0));
        atomicAdd(arow0 + 48 + 3 * k + 1, ALPHA * fmaf(t1_0, sm.svs[el0][1], ss0 * tv1_0));
        atomicAdd(arow0 + 48 + 3 * k + 2, ALPHA * fmaf(t1_0, sm.svs[el0][2], ss0 * tv2_0));
        atomicAdd(arow1 + 48 + 3 * k + 0, ALPHA * fmaf(t1_1, sm.svs[el0 + 32][0], ss1 * tv0_1));
        atomicAdd(arow1 + 48 + 3 * k + 1, ALPHA * fmaf(t1_1, sm.svs[el0 + 32][1], ss1 * tv1_1));
        atomicAdd(arow1 + 48 + 3 * k + 2, ALPHA * fmaf(t1_1, sm.svs[el0 + 32][2], ss1 * tv2_1));
    }
}

// ---------------- batchnorm statistics ----------------
__global__ __launch_bounds__(256) void k_stats(const float* __restrict__ bnw) {
    __shared__ float r1[256], r2[256];
    int b = blockIdx.x, t = threadIdx.x;
    float s1 = 0.f, s2 = 0.f;
    if (b < NSC) {
        for (int n = t; n < NNODES; n += 256) {
            float x = g_accum[(size_t)n * 96 + b];
            s1 += x;
            s2 += x * x;
        }
    } else {
        int k = b - NSC;
        for (int n = t; n < NNODES; n += 256) {
            const float* p = &g_accum[(size_t)n * 96 + 48 + 3 * k];
            float x0 = p[0], x1 = p[1], x2 = p[2];
            s2 += x0 * x0 + x1 * x1 + x2 * x2;
        }
    }
    r1[t] = s1;
    r2[t] = s2;
    __syncthreads();
    for (int off = 128; off > 0; off >>= 1) {
        if (t < off) {
            r1[t] += r1[t + off];
            r2[t] += r2[t + off];
        }
        __syncthreads();
    }
    if (t == 0) {
        if (b < NSC) {
            float mean = r1[0] / (float)NNODES;
            float var = r2[0] / (float)NNODES - mean * mean;
            g_mean[b] = mean;
            g_rs[b] = rsqrtf(var + BN_EPS) * bnw[b];
        } else {
            int k = b - NSC;
            float vn = r2[0] / (3.0f * (float)NNODES);
            g_rsv[k] = rsqrtf(vn + BN_EPS) * bnw[NSC + k];
        }
    }
}

// ---------------- final normalize ----------------
__global__ void k_final(const float* __restrict__ bnb, float* __restrict__ out) {
    int idx = blockIdx.x * 256 + threadIdx.x;
    if (idx >= NNODES * 96) return;
    int c = idx % 96;
    float x = g_accum[idx];
    float o;
    if (c < NSC) {
        o = (x - g_mean[c]) * g_rs[c] + bnb[c];
    } else {
        int k = (c - 48) / 3;
        o = x * g_rsv[k];
    }
    out[idx] = o;
}

// ---------------- launch ----------------
extern "C" void kernel_launch(void* const* d_in, const int* in_sizes, int n_in,
                              void* d_out, int out_size) {
    const float* node_attr = (const float*)d_in[0];
    const int* eidx_raw    = (const int*)d_in[1];
    const float* edge_attr = (const float*)d_in[2];
    const float* edge_sh   = (const float*)d_in[3];
    const float* fc_w1     = (const float*)d_in[4];
    const float* fc_b1     = (const float*)d_in[5];
    const float* fc_w2     = (const float*)d_in[6];
    const float* fc_b2     = (const float*)d_in[7];
    const float* bn_weight = (const float*)d_in[8];
    const float* bn_bias   = (const float*)d_in[9];
    float* out = (float*)d_out;

    cudaFuncSetAttribute(k_stage_b, cudaFuncAttributeMaxDynamicSharedMemorySize,
                         (int)sizeof(SmemB));

    k_detect_idx<<<1, 256>>>(eidx_raw);
    k_convert_idx<<<(NEDGES + 255) / 256, 256>>>(eidx_raw);
    k_transpose_w2<<<dim3(WNUM / 32, NEF / 32), dim3(32, 8)>>>(fc_w2);
    k_stage_a<<<NEDGES / 64, 256>>>(edge_attr, fc_w1, fc_b1);
    k_init_accum<<<(NNODES * 96 + 255) / 256, 256>>>(node_attr);
    k_stage_b<<<NEDGES / 64, 256, sizeof(SmemB)>>>(node_attr, edge_sh, fc_b2);
    k_stats<<<NSC + NVC, 256>>>(bn_weight);
    k_final<<<(NNODES * 96 + 255) / 256, 256>>>(bn_bias, out);
}

// round 3
// speedup vs baseline: 1.6229x; 1.6229x over previous
#include <cuda_runtime.h>

#define NNODES 4096
#define NEDGES 32768
#define NSC 48
#define NVC 16
#define NEF 128
#define WNUM 4096
#define BN_EPS 1e-5f
#define INV_SQRT3 0.57735026918962576f
#define ALPHA 0.125f

// ---------------- static device scratch ----------------
__device__ float g_H[NEDGES * NEF];     // H = relu(edge_attr @ W1 + b1), [e][kk]
__device__ float g_W2p[WNUM * NEF];     // fc_w2 transposed: [j][kk]
__device__ float g_accum[NNODES * 96];  // node_attr + segment_sum(msg)
__device__ float g_mean[NSC];
__device__ float g_rs[NSC];
__device__ float g_rsv[NVC];
__device__ int g_src[NEDGES];
__device__ int g_dst[NEDGES];
__device__ int g_mode;

// ---------------- edge_index dtype detection + conversion ----------------
__global__ void k_detect_idx(const int* __restrict__ raw) {
    __shared__ int flag;
    int t = threadIdx.x;
    if (t == 0) flag = 0;
    __syncthreads();
    for (int i = t; i < 2048; i += 256) {
        if (raw[2 * i + 1] != 0) flag = 1;
    }
    __syncthreads();
    if (t == 0) g_mode = flag;
}

__global__ void k_convert_idx(const int* __restrict__ raw) {
    int e = blockIdx.x * 256 + threadIdx.x;
    if (e >= NEDGES) return;
    if (g_mode) {
        g_src[e] = raw[e];
        g_dst[e] = raw[NEDGES + e];
    } else {
        g_src[e] = raw[2 * e];
        g_dst[e] = raw[2 * (NEDGES + e)];
    }
}

// ---------------- W2 transpose: [kk][j] -> [j][kk] ----------------
__global__ void k_transpose_w2(const float* __restrict__ w2) {
    __shared__ float tile[32][33];
    int j0 = blockIdx.x * 32;
    int k0 = blockIdx.y * 32;
    int tx = threadIdx.x, ty = threadIdx.y;
#pragma unroll
    for (int r = ty; r < 32; r += 8)
        tile[r][tx] = w2[(size_t)(k0 + r) * WNUM + j0 + tx];
    __syncthreads();
#pragma unroll
    for (int r = ty; r < 32; r += 8)
        g_W2p[(size_t)(j0 + r) * NEF + k0 + tx] = tile[tx][r];
}

// ---------------- Stage A: H = relu(edge_attr @ W1 + b1) ----------------
__global__ __launch_bounds__(256) void k_stage_a(const float* __restrict__ ea,
                                                 const float* __restrict__ w1,
                                                 const float* __restrict__ b1) {
    __shared__ float As[32][65];
    __shared__ float Ws[32][128];
    int t = threadIdx.x;
    int tx = t & 31, ty = t >> 5;
    int e0 = blockIdx.x * 64;
    float acc[8][4];
#pragma unroll
    for (int i = 0; i < 8; ++i)
#pragma unroll
        for (int j = 0; j < 4; ++j) acc[i][j] = 0.f;

    for (int k0 = 0; k0 < NEF; k0 += 32) {
        for (int idx = t; idx < 64 * 32; idx += 256) {
            int e = idx >> 5, kk = idx & 31;
            As[kk][e] = ea[(size_t)(e0 + e) * NEF + k0 + kk];
        }
        for (int idx = t; idx < 32 * 128; idx += 256) {
            int kk = idx >> 7, cc = idx & 127;
            Ws[kk][cc] = w1[(size_t)(k0 + kk) * NEF + cc];
        }
        __syncthreads();
#pragma unroll 8
        for (int kk = 0; kk < 32; ++kk) {
            float4 b = *reinterpret_cast<const float4*>(&Ws[kk][tx * 4]);
#pragma unroll
            for (int i = 0; i < 8; ++i) {
                float a = As[kk][ty * 8 + i];
                acc[i][0] = fmaf(a, b.x, acc[i][0]);
                acc[i][1] = fmaf(a, b.y, acc[i][1]);
                acc[i][2] = fmaf(a, b.z, acc[i][2]);
                acc[i][3] = fmaf(a, b.w, acc[i][3]);
            }
        }
        __syncthreads();
    }
    float4 bias = *reinterpret_cast<const float4*>(&b1[tx * 4]);
#pragma unroll
    for (int i = 0; i < 8; ++i) {
        float4 o;
        o.x = fmaxf(acc[i][0] + bias.x, 0.f);
        o.y = fmaxf(acc[i][1] + bias.y, 0.f);
        o.z = fmaxf(acc[i][2] + bias.z, 0.f);
        o.w = fmaxf(acc[i][3] + bias.w, 0.f);
        *reinterpret_cast<float4*>(&g_H[(size_t)(e0 + ty * 8 + i) * NEF + tx * 4]) = o;
    }
}

// ---------------- accumulator init with residual ----------------
__global__ void k_init_accum(const float* __restrict__ na) {
    int idx = blockIdx.x * 256 + threadIdx.x;
    if (idx < NNODES * 96) g_accum[idx] = na[idx];
}

// ---------------- Stage B ----------------
struct SmemB {
    float Hs[NEF][65];     // [kk][e] padded
    float coefT[64][64];   // [i][e]
    float xssT[48][64];    // [i][e]
    float xvsT[48][64];    // [3*i+m][e]
    float svs[64][3];
    float sss[64];
    int dsts[64];
    int srcs[64];
};

__device__ __forceinline__ float dlrelu(float x) {
    return (fabsf(x) <= 10.f) ? x : 0.01f * x;
}

// 8 W2 rows (compile-time stride RS4 in float4 units) dotted against 2 H columns.
template <int RS4>
__device__ __forceinline__ void dot8x2(const float4* __restrict__ wb,
                                       const float* __restrict__ hs,
                                       int el0, float c0[8], float c1[8]) {
#pragma unroll
    for (int ti = 0; ti < 8; ++ti) { c0[ti] = 0.f; c1[ti] = 0.f; }
#pragma unroll 2
    for (int kkc = 0; kkc < 32; ++kkc) {
        float h00 = hs[(4 * kkc + 0) * 65 + el0];
        float h01 = hs[(4 * kkc + 1) * 65 + el0];
        float h02 = hs[(4 * kkc + 2) * 65 + el0];
        float h03 = hs[(4 * kkc + 3) * 65 + el0];
        float h10 = hs[(4 * kkc + 0) * 65 + el0 + 32];
        float h11 = hs[(4 * kkc + 1) * 65 + el0 + 32];
        float h12 = hs[(4 * kkc + 2) * 65 + el0 + 32];
        float h13 = hs[(4 * kkc + 3) * 65 + el0 + 32];
#pragma unroll
        for (int ti = 0; ti < 8; ++ti) {
            float4 w = __ldg(wb + ti * RS4 + kkc);
            c0[ti] = fmaf(h00, w.x, c0[ti]);
            c0[ti] = fmaf(h01, w.y, c0[ti]);
            c0[ti] = fmaf(h02, w.z, c0[ti]);
            c0[ti] = fmaf(h03, w.w, c0[ti]);
            c1[ti] = fmaf(h10, w.x, c1[ti]);
            c1[ti] = fmaf(h11, w.y, c1[ti]);
            c1[ti] = fmaf(h12, w.z, c1[ti]);
            c1[ti] = fmaf(h13, w.w, c1[ti]);
        }
    }
}

extern __shared__ char smem_raw[];

__global__ __launch_bounds__(256, 2) void k_stage_b(const float* __restrict__ na,
                                                    const float* __restrict__ sh,
                                                    const float* __restrict__ b2) {
    SmemB& sm = *reinterpret_cast<SmemB*>(smem_raw);
    int t = threadIdx.x;
    int e0 = blockIdx.x * 64;

    if (t < 64) {
        int e = e0 + t;
        sm.srcs[t] = g_src[e];
        sm.dsts[t] = g_dst[e];
        float4 shv = __ldg(reinterpret_cast<const float4*>(sh) + e);
        sm.sss[t] = shv.x;
        sm.svs[t][0] = shv.y;
        sm.svs[t][1] = shv.z;
        sm.svs[t][2] = shv.w;
    }
    __syncthreads();
    // gather node_attr[src] (transposed layouts)
    for (int idx = t; idx < 64 * 96; idx += 256) {
        int e = idx / 96, c = idx % 96;
        float v = na[(size_t)sm.srcs[e] * 96 + c];
        if (c < 48) sm.xssT[c][e] = v;
        else sm.xvsT[c - 48][e] = v;
    }
    // H tile
    for (int idx = t; idx < 64 * NEF; idx += 256) {
        int e = idx >> 7, kk = idx & 127;
        sm.Hs[kk][e] = g_H[(size_t)(e0 + e) * NEF + kk];
    }
    __syncthreads();
    // scalar-path coefficients
    for (int idx = t; idx < 64 * 64; idx += 256) {
        int e = idx >> 6, i = idx & 63;
        float v;
        if (i < 48) {
            v = sm.xssT[i][e] * sm.sss[e];
        } else {
            int i2 = i - 48;
            v = INV_SQRT3 * (sm.xvsT[3 * i2 + 0][e] * sm.svs[e][0]
                           + sm.xvsT[3 * i2 + 1][e] * sm.svs[e][1]
                           + sm.xvsT[3 * i2 + 2][e] * sm.svs[e][2]);
        }
        sm.coefT[i][e] = v;
    }
    __syncthreads();

    int el0 = t & 31;          // lane: first edge; second is el0+32
    int kg = t >> 5;           // warp id 0..7: k residue
    const float* hs = &sm.Hs[0][0];
    float* arow0 = g_accum + (size_t)sm.dsts[el0] * 96;
    float* arow1 = g_accum + (size_t)sm.dsts[el0 + 32] * 96;

    // ---- scalar outputs: k = kg + 8u ----
#pragma unroll 1
    for (int u = 0; u < 6; ++u) {
        int k = kg + 8 * u;
        float acc0 = 0.f, acc1 = 0.f;
#pragma unroll 1
        for (int i0 = 0; i0 < 64; i0 += 8) {
            float c0[8], c1[8];
            const float4* wb = reinterpret_cast<const float4*>(
                g_W2p + (size_t)(i0 * 48 + k) * NEF);
            dot8x2<48 * 32>(wb, hs, el0, c0, c1);
#pragma unroll
            for (int ti = 0; ti < 8; ++ti) {
                float b = __ldg(b2 + (i0 + ti) * 48 + k);
                float cf0 = sm.coefT[i0 + ti][el0];
                float cf1 = sm.coefT[i0 + ti][el0 + 32];
                acc0 = fmaf(cf0, dlrelu(c0[ti] + b), acc0);
                acc1 = fmaf(cf1, dlrelu(c1[ti] + b), acc1);
            }
        }
        atomicAdd(arow0 + k, ALPHA * acc0);
        atomicAdd(arow1 + k, ALPHA * acc1);
    }

    // ---- vector outputs: k = kg + 8u, u in {0,1} ----
#pragma unroll 1
    for (int u = 0; u < 2; ++u) {
        int k = kg + 8 * u;
        float t1_0 = 0.f, t1_1 = 0.f;
        float tv0_0 = 0.f, tv1_0 = 0.f, tv2_0 = 0.f;
        float tv0_1 = 0.f, tv1_1 = 0.f, tv2_1 = 0.f;
#pragma unroll 1
        for (int i0 = 0; i0 < 48; i0 += 8) {  // w_sv block
            float c0[8], c1[8];
            const float4* wb = reinterpret_cast<const float4*>(
                g_W2p + (size_t)(3072 + i0 * 16 + k) * NEF);
            dot8x2<16 * 32>(wb, hs, el0, c0, c1);
#pragma unroll
            for (int ti = 0; ti < 8; ++ti) {
                float b = __ldg(b2 + 3072 + (i0 + ti) * 16 + k);
                float xs0 = sm.xssT[i0 + ti][el0];
                float xs1 = sm.xssT[i0 + ti][el0 + 32];
                t1_0 = fmaf(xs0, dlrelu(c0[ti] + b), t1_0);
                t1_1 = fmaf(xs1, dlrelu(c1[ti] + b), t1_1);
            }
        }
#pragma unroll 1
        for (int i0 = 0; i0 < 16; i0 += 8) {  // w_vv block
            float c0[8], c1[8];
            const float4* wb = reinterpret_cast<const float4*>(
                g_W2p + (size_t)(3840 + i0 * 16 + k) * NEF);
            dot8x2<16 * 32>(wb, hs, el0, c0, c1);
#pragma unroll
            for (int ti = 0; ti < 8; ++ti) {
                int i = i0 + ti;
                float b = __ldg(b2 + 3840 + i * 16 + k);
                float w0 = dlrelu(c0[ti] + b);
                float w1 = dlrelu(c1[ti] + b);
                tv0_0 = fmaf(sm.xvsT[3 * i + 0][el0], w0, tv0_0);
                tv1_0 = fmaf(sm.xvsT[3 * i + 1][el0], w0, tv1_0);
                tv2_0 = fmaf(sm.xvsT[3 * i + 2][el0], w0, tv2_0);
                tv0_1 = fmaf(sm.xvsT[3 * i + 0][el0 + 32], w1, tv0_1);
                tv1_1 = fmaf(sm.xvsT[3 * i + 1][el0 + 32], w1, tv1_1);
                tv2_1 = fmaf(sm.xvsT[3 * i + 2][el0 + 32], w1, tv2_1);
            }
        }
        float ss0 = sm.sss[el0], ss1 = sm.sss[el0 + 32];
        atomicAdd(arow0 + 48 + 3 * k + 0, ALPHA * fmaf(t1_0, sm.svs[el0][0], ss0 * tv0_0));
        atomicAdd(arow0 + 48 + 3 * k + 1, ALPHA * fmaf(t1_0, sm.svs[el0][1], ss0 * tv1_0));
        atomicAdd(arow0 + 48 + 3 * k + 2, ALPHA * fmaf(t1_0, sm.svs[el0][2], ss0 * tv2_0));
        atomicAdd(arow1 + 48 + 3 * k + 0, ALPHA * fmaf(t1_1, sm.svs[el0 + 32][0], ss1 * tv0_1));
        atomicAdd(arow1 + 48 + 3 * k + 1, ALPHA * fmaf(t1_1, sm.svs[el0 + 32][1], ss1 * tv1_1));
        atomicAdd(arow1 + 48 + 3 * k + 2, ALPHA * fmaf(t1_1, sm.svs[el0 + 32][2], ss1 * tv2_1));
    }
}

// ---------------- batchnorm statistics ----------------
__global__ __launch_bounds__(256) void k_stats(const float* __restrict__ bnw) {
    __shared__ float r1[256], r2[256];
    int b = blockIdx.x, t = threadIdx.x;
    float s1 = 0.f, s2 = 0.f;
    if (b < NSC) {
        for (int n = t; n < NNODES; n += 256) {
            float x = g_accum[(size_t)n * 96 + b];
            s1 += x;
            s2 += x * x;
        }
    } else {
        int k = b - NSC;
        for (int n = t; n < NNODES; n += 256) {
            const float* p = &g_accum[(size_t)n * 96 + 48 + 3 * k];
            float x0 = p[0], x1 = p[1], x2 = p[2];
            s2 += x0 * x0 + x1 * x1 + x2 * x2;
        }
    }
    r1[t] = s1;
    r2[t] = s2;
    __syncthreads();
    for (int off = 128; off > 0; off >>= 1) {
        if (t < off) {
            r1[t] += r1[t + off];
            r2[t] += r2[t + off];
        }
        __syncthreads();
    }
    if (t == 0) {
        if (b < NSC) {
            float mean = r1[0] / (float)NNODES;
            float var = r2[0] / (float)NNODES - mean * mean;
            g_mean[b] = mean;
            g_rs[b] = rsqrtf(var + BN_EPS) * bnw[b];
        } else {
            int k = b - NSC;
            float vn = r2[0] / (3.0f * (float)NNODES);
            g_rsv[k] = rsqrtf(vn + BN_EPS) * bnw[NSC + k];
        }
    }
}

// ---------------- final normalize ----------------
__global__ void k_final(const float* __restrict__ bnb, float* __restrict__ out) {
    int idx = blockIdx.x * 256 + threadIdx.x;
    if (idx >= NNODES * 96) return;
    int c = idx % 96;
    float x = g_accum[idx];
    float o;
    if (c < NSC) {
        o = (x - g_mean[c]) * g_rs[c] + bnb[c];
    } else {
        int k = (c - 48) / 3;
        o = x * g_rsv[k];
    }
    out[idx] = o;
}

// ---------------- launch ----------------
extern "C" void kernel_launch(void* const* d_in, const int* in_sizes, int n_in,
                              void* d_out, int out_size) {
    const float* node_attr = (const float*)d_in[0];
    const int* eidx_raw    = (const int*)d_in[1];
    const float* edge_attr = (const float*)d_in[2];
    const float* edge_sh   = (const float*)d_in[3];
    const float* fc_w1     = (const float*)d_in[4];
    const float* fc_b1     = (const float*)d_in[5];
    const float* fc_w2     = (const float*)d_in[6];
    const float* fc_b2     = (const float*)d_in[7];
    const float* bn_weight = (const float*)d_in[8];
    const float* bn_bias   = (const float*)d_in[9];
    float* out = (float*)d_out;

    cudaFuncSetAttribute(k_stage_b, cudaFuncAttributeMaxDynamicSharedMemorySize,
                         (int)sizeof(SmemB));

    k_detect_idx<<<1, 256>>>(eidx_raw);
    k_convert_idx<<<(NEDGES + 255) / 256, 256>>>(eidx_raw);
    k_transpose_w2<<<dim3(WNUM / 32, NEF / 32), dim3(32, 8)>>>(fc_w2);
    k_stage_a<<<NEDGES / 64, 256>>>(edge_attr, fc_w1, fc_b1);
    k_init_accum<<<(NNODES * 96 + 255) / 256, 256>>>(node_attr);
    k_stage_b<<<NEDGES / 64, 256, sizeof(SmemB)>>>(node_attr, edge_sh, fc_b2);
    k_stats<<<NSC + NVC, 256>>>(bn_weight);
    k_final<<<(NNODES * 96 + 255) / 256, 256>>>(bn_bias, out);
}

// round 5
// speedup vs baseline: 6.6369x; 4.0894x over previous
#include <cuda_runtime.h>
#include <stdint.h>

#define NNODES 4096
#define NEDGES 32768
#define NSC 48
#define NVC 16
#define NEF 128
#define WNUM 4096
#define BN_EPS 1e-5f
#define INV_SQRT3 0.57735026918962576f
#define ALPHA 0.125f

#define NCHUNKS 64
#define KSTEPS 17              // 16 data ksteps + 1 bias kstep
#define BFRAG_PER_CHUNK (KSTEPS * 8 * 32)   // float2 entries = 4352
#define BFRAG_BYTES (BFRAG_PER_CHUNK * 8)   // 34816

// ---------------- static device scratch ----------------
__device__ float g_H[NEDGES * NEF];                 // H = relu(ea @ W1 + b1) fp32
__device__ float g_W2p[WNUM * NEF];                 // fc_w2 transposed [j][kk]
__device__ __align__(16) float2 g_Bfrag[NCHUNKS * BFRAG_PER_CHUNK];  // tf32 fragment images
__device__ float g_accum[NNODES * 96];
__device__ float g_mean[NSC];
__device__ float g_rs[NSC];
__device__ float g_rsv[NVC];
__device__ int g_src[NEDGES];
__device__ int g_dst[NEDGES];
__device__ int g_mode;

// ================= helpers =================
__device__ __forceinline__ uint32_t smem_u32(const void* p) {
    uint32_t a;
    asm("{ .reg .u64 t; cvta.to.shared.u64 t, %1; cvt.u32.u64 %0, t; }" : "=r"(a) : "l"(p));
    return a;
}
__device__ __forceinline__ uint32_t tf32c(float x) {
    uint32_t r;
    asm("cvt.rna.tf32.f32 %0, %1;" : "=r"(r) : "f"(x));
    return r;
}
__device__ __forceinline__ void mma8(float* d, const uint32_t* a, uint32_t b0, uint32_t b1) {
    asm volatile(
        "mma.sync.aligned.m16n8k8.row.col.f32.tf32.tf32.f32 "
        "{%0,%1,%2,%3}, {%4,%5,%6,%7}, {%8,%9}, {%0,%1,%2,%3};\n"
        : "+f"(d[0]), "+f"(d[1]), "+f"(d[2]), "+f"(d[3])
        : "r"(a[0]), "r"(a[1]), "r"(a[2]), "r"(a[3]), "r"(b0), "r"(b1));
}
__device__ __forceinline__ void cpa16(uint32_t s, const void* g) {
    asm volatile("cp.async.ca.shared.global [%0], [%1], 16;" :: "r"(s), "l"(g));
}
#define CP_COMMIT() asm volatile("cp.async.commit_group;" ::: "memory")
#define CP_WAIT0()  asm volatile("cp.async.wait_group 0;" ::: "memory")

__device__ __forceinline__ float dlrelu(float x) { return (fabsf(x) <= 10.f) ? x : 0.01f * x; }

// column permutation: jp (permuted) -> original j of fc_w2
__device__ __forceinline__ int jorig_of(int jp) {
    int chunk = jp >> 6, q = jp & 63;
    if (chunk < 48) {  // scalar output k = chunk
        return (q < 48) ? q * 48 + chunk : 2304 + (q - 48) * 48 + chunk;
    }
    int k = chunk - 48;  // vector output k
    return (q < 48) ? 3072 + q * 16 + k : 3840 + (q - 48) * 16 + k;
}

// ================= small prep kernels =================
__global__ void k_detect_idx(const int* __restrict__ raw) {
    __shared__ int flag;
    int t = threadIdx.x;
    if (t == 0) flag = 0;
    __syncthreads();
    for (int i = t; i < 2048; i += 256)
        if (raw[2 * i + 1] != 0) flag = 1;
    __syncthreads();
    if (t == 0) g_mode = flag;
}
__global__ void k_convert_idx(const int* __restrict__ raw) {
    int e = blockIdx.x * 256 + threadIdx.x;
    if (e >= NEDGES) return;
    if (g_mode) { g_src[e] = raw[e]; g_dst[e] = raw[NEDGES + e]; }
    else        { g_src[e] = raw[2 * e]; g_dst[e] = raw[2 * (NEDGES + e)]; }
}
__global__ void k_transpose_w2(const float* __restrict__ w2) {
    __shared__ float tile[32][33];
    int j0 = blockIdx.x * 32, k0 = blockIdx.y * 32;
    int tx = threadIdx.x, ty = threadIdx.y;
#pragma unroll
    for (int r = ty; r < 32; r += 8)
        tile[r][tx] = w2[(size_t)(k0 + r) * WNUM + j0 + tx];
    __syncthreads();
#pragma unroll
    for (int r = ty; r < 32; r += 8)
        g_W2p[(size_t)(j0 + r) * NEF + k0 + tx] = tile[tx][r];
}
// build tf32 B fragment images: [chunk][kstep][n8][lane] -> {b0,b1}
__global__ void k_prep_bf(const float* __restrict__ b2) {
    int idx = blockIdx.x * 256 + threadIdx.x;
    if (idx >= NCHUNKS * BFRAG_PER_CHUNK) return;
    int lane = idx & 31;
    int g8 = (idx >> 5) & 7;
    int rest = idx >> 8;        // chunk*17 + s
    int s = rest % 17, chunk = rest / 17;
    int q = g8 * 8 + (lane >> 2);
    int jo = jorig_of(chunk * 64 + q);
    int k0 = s * 8 + (lane & 3), k1 = k0 + 4;
    float f0 = (k0 < 128) ? g_W2p[jo * 128 + k0] : ((k0 == 128) ? b2[jo] : 0.f);
    float f1 = (k1 < 128) ? g_W2p[jo * 128 + k1] : ((k1 == 128) ? b2[jo] : 0.f);
    float2 out;
    out.x = __uint_as_float(tf32c(f0));
    out.y = __uint_as_float(tf32c(f1));
    g_Bfrag[idx] = out;
}

// ---------------- Stage A: H = relu(ea @ W1 + b1) fp32 ----------------
__global__ __launch_bounds__(256) void k_stage_a(const float* __restrict__ ea,
                                                 const float* __restrict__ w1,
                                                 const float* __restrict__ b1) {
    __shared__ float As[32][65];
    __shared__ float Ws[32][128];
    int t = threadIdx.x;
    int tx = t & 31, ty = t >> 5;
    int e0 = blockIdx.x * 64;
    float acc[8][4];
#pragma unroll
    for (int i = 0; i < 8; ++i)
#pragma unroll
        for (int j = 0; j < 4; ++j) acc[i][j] = 0.f;

    for (int k0 = 0; k0 < NEF; k0 += 32) {
        for (int idx = t; idx < 64 * 32; idx += 256) {
            int e = idx >> 5, kk = idx & 31;
            As[kk][e] = ea[(size_t)(e0 + e) * NEF + k0 + kk];
        }
        for (int idx = t; idx < 32 * 128; idx += 256) {
            int kk = idx >> 7, cc = idx & 127;
            Ws[kk][cc] = w1[(size_t)(k0 + kk) * NEF + cc];
        }
        __syncthreads();
#pragma unroll 8
        for (int kk = 0; kk < 32; ++kk) {
            float4 b = *reinterpret_cast<const float4*>(&Ws[kk][tx * 4]);
#pragma unroll
            for (int i = 0; i < 8; ++i) {
                float a = As[kk][ty * 8 + i];
                acc[i][0] = fmaf(a, b.x, acc[i][0]);
                acc[i][1] = fmaf(a, b.y, acc[i][1]);
                acc[i][2] = fmaf(a, b.z, acc[i][2]);
                acc[i][3] = fmaf(a, b.w, acc[i][3]);
            }
        }
        __syncthreads();
    }
    float4 bias = *reinterpret_cast<const float4*>(&b1[tx * 4]);
#pragma unroll
    for (int i = 0; i < 8; ++i) {
        float4 o;
        o.x = fmaxf(acc[i][0] + bias.x, 0.f);
        o.y = fmaxf(acc[i][1] + bias.y, 0.f);
        o.z = fmaxf(acc[i][2] + bias.z, 0.f);
        o.w = fmaxf(acc[i][3] + bias.w, 0.f);
        *reinterpret_cast<float4*>(&g_H[(size_t)(e0 + ty * 8 + i) * NEF + tx * 4]) = o;
    }
}

__global__ void k_init_accum(const float* __restrict__ na) {
    int idx = blockIdx.x * 256 + threadIdx.x;
    if (idx < NNODES * 96) g_accum[idx] = na[idx];
}

// ================= fused mma.sync GEMM + tensor product + scatter =================
struct SmemT {
    uint2 B[2][BFRAG_PER_CHUNK];   // 2 x 34816 B
    float coefS[128][65];          // q<48: xs*ss ; q>=48: dot
    float xs[128][49];
    float xv[128][49];
    float sss[128];
    float sv[128][3];
    int dst[128];
};

extern __shared__ __align__(16) char smemraw[];

__global__ __launch_bounds__(256, 1) void k_tp(const float* __restrict__ na,
                                               const float* __restrict__ sh) {
    SmemT& sm = *reinterpret_cast<SmemT*>(smemraw);
    int t = threadIdx.x, lane = t & 31, w = t >> 5;
    int h = w & 1;                 // n-half
    int mb = (w >> 1) * 32;        // m-block base (32 edges per warp)
    int ctile = blockIdx.x;
    int ebase = ctile * 128;

    // issue cp.async for chunk 0 -> buf 0
    {
        uint32_t sB = smem_u32(&sm.B[0][0]);
        const char* g = (const char*)g_Bfrag;
#pragma unroll
        for (int i = 0; i < 9; ++i) {
            int idx = t + 256 * i;
            if (idx < BFRAG_BYTES / 16) cpa16(sB + idx * 16, g + idx * 16);
        }
        CP_COMMIT();
    }

    // per-edge setup (threads 0..127)
    if (t < 128) {
        int e = ebase + t;
        sm.dst[t] = g_dst[e];
        float4 shv = __ldg(reinterpret_cast<const float4*>(sh) + e);
        sm.sss[t] = shv.x;
        sm.sv[t][0] = shv.y; sm.sv[t][1] = shv.z; sm.sv[t][2] = shv.w;
        const float4* nr = reinterpret_cast<const float4*>(na + (size_t)g_src[e] * 96);
#pragma unroll
        for (int q = 0; q < 24; ++q) {
            float4 v = __ldg(nr + q);
            float vv[4] = {v.x, v.y, v.z, v.w};
#pragma unroll
            for (int j = 0; j < 4; ++j) {
                int c = q * 4 + j;
                if (c < 48) sm.xs[t][c] = vv[j];
                else sm.xv[t][c - 48] = vv[j];
            }
        }
#pragma unroll
        for (int i = 0; i < 16; ++i)
            sm.coefS[t][48 + i] = INV_SQRT3 * (sm.xv[t][3 * i + 0] * shv.y +
                                               sm.xv[t][3 * i + 1] * shv.z +
                                               sm.xv[t][3 * i + 2] * shv.w);
#pragma unroll
        for (int q = 0; q < 48; ++q)
            sm.coefS[t][q] = sm.xs[t][q] * shv.x;
    }

    // load A fragments (tf32) into registers, reused across all 64 chunks
    uint32_t a[2][KSTEPS][4];
    int e0 = ebase + mb + (lane >> 2);
#pragma unroll
    for (int mt = 0; mt < 2; ++mt) {
        const float* p0 = g_H + (size_t)(e0 + mt * 16) * NEF;
        const float* p1 = p0 + 8 * NEF;
#pragma unroll
        for (int s = 0; s < 16; ++s) {
            int k0 = s * 8 + (lane & 3);
            a[mt][s][0] = tf32c(__ldg(p0 + k0));
            a[mt][s][1] = tf32c(__ldg(p1 + k0));
            a[mt][s][2] = tf32c(__ldg(p0 + k0 + 4));
            a[mt][s][3] = tf32c(__ldg(p1 + k0 + 4));
        }
        uint32_t one = ((lane & 3) == 0) ? 0x3f800000u : 0u;
        a[mt][16][0] = one; a[mt][16][1] = one;
        a[mt][16][2] = 0u;  a[mt][16][3] = 0u;
    }

#pragma unroll 1
    for (int c = 0; c < NCHUNKS; ++c) {
        int p = c & 1;
        CP_WAIT0();
        __syncthreads();
        // prefetch next chunk into other buffer
        if (c + 1 < NCHUNKS) {
            uint32_t sB = smem_u32(&sm.B[1 - p][0]);
            const char* g = (const char*)(g_Bfrag + (size_t)(c + 1) * BFRAG_PER_CHUNK);
#pragma unroll
            for (int i = 0; i < 9; ++i) {
                int idx = t + 256 * i;
                if (idx < BFRAG_BYTES / 16) cpa16(sB + idx * 16, g + idx * 16);
            }
            CP_COMMIT();
        }
        // ---- MMA: m32 x n32 per warp, K=136 ----
        float acc[2][4][4];
#pragma unroll
        for (int mt = 0; mt < 2; ++mt)
#pragma unroll
            for (int b = 0; b < 4; ++b)
#pragma unroll
                for (int r = 0; r < 4; ++r) acc[mt][b][r] = 0.f;
#pragma unroll
        for (int s = 0; s < KSTEPS; ++s) {
#pragma unroll
            for (int b = 0; b < 4; ++b) {
                uint2 bf = sm.B[p][(s * 8 + h * 4 + b) * 32 + lane];
                mma8(acc[0][b], a[0][s], bf.x, bf.y);
                mma8(acc[1][b], a[1][s], bf.x, bf.y);
            }
        }
        // ---- epilogue ----
        if (c < 48) {
            // scalar output chunk c: coefS contraction
            float ps[2][2] = {{0.f, 0.f}, {0.f, 0.f}};
#pragma unroll
            for (int mt = 0; mt < 2; ++mt) {
                int el0 = mb + mt * 16 + (lane >> 2);
#pragma unroll
                for (int b = 0; b < 4; ++b) {
                    int q0 = (h * 4 + b) * 8 + (lane & 3) * 2;
                    float w00 = dlrelu(acc[mt][b][0]), w01 = dlrelu(acc[mt][b][1]);
                    float w10 = dlrelu(acc[mt][b][2]), w11 = dlrelu(acc[mt][b][3]);
                    ps[mt][0] += sm.coefS[el0][q0] * w00 + sm.coefS[el0][q0 + 1] * w01;
                    ps[mt][1] += sm.coefS[el0 + 8][q0] * w10 + sm.coefS[el0 + 8][q0 + 1] * w11;
                }
            }
#pragma unroll
            for (int mt = 0; mt < 2; ++mt)
#pragma unroll
                for (int rh = 0; rh < 2; ++rh) {
                    float v = ps[mt][rh];
                    v += __shfl_xor_sync(0xffffffffu, v, 1);
                    v += __shfl_xor_sync(0xffffffffu, v, 2);
                    ps[mt][rh] = v;
                }
            int j = lane & 3;
            float out = (j == 0) ? ps[0][0] : (j == 1) ? ps[0][1]
                      : (j == 2) ? ps[1][0] : ps[1][1];
            int el = mb + (j >> 1) * 16 + (j & 1) * 8 + (lane >> 2);
            atomicAdd(g_accum + (size_t)sm.dst[el] * 96 + c, ALPHA * out);
        } else {
            // vector output chunk: k = c - 48
            int kk = c - 48;
            float t1[2][2] = {{0.f, 0.f}, {0.f, 0.f}};
            float tv[2][2][3];
#pragma unroll
            for (int mt = 0; mt < 2; ++mt)
#pragma unroll
                for (int rh = 0; rh < 2; ++rh)
#pragma unroll
                    for (int m = 0; m < 3; ++m) tv[mt][rh][m] = 0.f;
#pragma unroll
            for (int mt = 0; mt < 2; ++mt) {
                int el0 = mb + mt * 16 + (lane >> 2);
#pragma unroll
                for (int b = 0; b < 4; ++b) {
                    int g8 = h * 4 + b;
                    int q0 = g8 * 8 + (lane & 3) * 2;
                    float w00 = dlrelu(acc[mt][b][0]), w01 = dlrelu(acc[mt][b][1]);
                    float w10 = dlrelu(acc[mt][b][2]), w11 = dlrelu(acc[mt][b][3]);
                    if (g8 < 6) {  // q < 48: xs path (uniform per block)
                        t1[mt][0] += sm.xs[el0][q0] * w00 + sm.xs[el0][q0 + 1] * w01;
                        t1[mt][1] += sm.xs[el0 + 8][q0] * w10 + sm.xs[el0 + 8][q0 + 1] * w11;
                    } else {       // q >= 48: xv path
                        int i0 = q0 - 48;
#pragma unroll
                        for (int m = 0; m < 3; ++m) {
                            tv[mt][0][m] += sm.xv[el0][3 * i0 + m] * w00 +
                                            sm.xv[el0][3 * (i0 + 1) + m] * w01;
                            tv[mt][1][m] += sm.xv[el0 + 8][3 * i0 + m] * w10 +
                                            sm.xv[el0 + 8][3 * (i0 + 1) + m] * w11;
                        }
                    }
                }
            }
#pragma unroll
            for (int mt = 0; mt < 2; ++mt)
#pragma unroll
                for (int rh = 0; rh < 2; ++rh) {
                    float v = t1[mt][rh];
                    v += __shfl_xor_sync(0xffffffffu, v, 1);
                    v += __shfl_xor_sync(0xffffffffu, v, 2);
                    t1[mt][rh] = v;
#pragma unroll
                    for (int m = 0; m < 3; ++m) {
                        float u = tv[mt][rh][m];
                        u += __shfl_xor_sync(0xffffffffu, u, 1);
                        u += __shfl_xor_sync(0xffffffffu, u, 2);
                        tv[mt][rh][m] = u;
                    }
                }
            int j = lane & 3;
            float t1j = (j == 0) ? t1[0][0] : (j == 1) ? t1[0][1]
                      : (j == 2) ? t1[1][0] : t1[1][1];
            float tvj[3];
#pragma unroll
            for (int m = 0; m < 3; ++m)
                tvj[m] = (j == 0) ? tv[0][0][m] : (j == 1) ? tv[0][1][m]
                       : (j == 2) ? tv[1][0][m] : tv[1][1][m];
            int el = mb + (j >> 1) * 16 + (j & 1) * 8 + (lane >> 2);
            float ssv = sm.sss[el];
            float* base = g_accum + (size_t)sm.dst[el] * 96 + 48 + 3 * kk;
#pragma unroll
            for (int m = 0; m < 3; ++m)
                atomicAdd(base + m, ALPHA * fmaf(t1j, sm.sv[el][m], ssv * tvj[m]));
        }
    }
}

// ---------------- batchnorm statistics ----------------
__global__ __launch_bounds__(256) void k_stats(const float* __restrict__ bnw) {
    __shared__ float r1[256], r2[256];
    int b = blockIdx.x, t = threadIdx.x;
    float s1 = 0.f, s2 = 0.f;
    if (b < NSC) {
        for (int n = t; n < NNODES; n += 256) {
            float x = g_accum[(size_t)n * 96 + b];
            s1 += x;
            s2 += x * x;
        }
    } else {
        int k = b - NSC;
        for (int n = t; n < NNODES; n += 256) {
            const float* p = &g_accum[(size_t)n * 96 + 48 + 3 * k];
            s2 += p[0] * p[0] + p[1] * p[1] + p[2] * p[2];
        }
    }
    r1[t] = s1;
    r2[t] = s2;
    __syncthreads();
    for (int off = 128; off > 0; off >>= 1) {
        if (t < off) { r1[t] += r1[t + off]; r2[t] += r2[t + off]; }
        __syncthreads();
    }
    if (t == 0) {
        if (b < NSC) {
            float mean = r1[0] / (float)NNODES;
            float var = r2[0] / (float)NNODES - mean * mean;
            g_mean[b] = mean;
            g_rs[b] = rsqrtf(var + BN_EPS) * bnw[b];
        } else {
            int k = b - NSC;
            float vn = r2[0] / (3.0f * (float)NNODES);
            g_rsv[k] = rsqrtf(vn + BN_EPS) * bnw[NSC + k];
        }
    }
}

__global__ void k_final(const float* __restrict__ bnb, float* __restrict__ out) {
    int idx = blockIdx.x * 256 + threadIdx.x;
    if (idx >= NNODES * 96) return;
    int c = idx % 96;
    float x = g_accum[idx];
    float o;
    if (c < NSC) o = (x - g_mean[c]) * g_rs[c] + bnb[c];
    else         o = x * g_rsv[(c - 48) / 3];
    out[idx] = o;
}

// ---------------- launch ----------------
extern "C" void kernel_launch(void* const* d_in, const int* in_sizes, int n_in,
                              void* d_out, int out_size) {
    const float* node_attr = (const float*)d_in[0];
    const int* eidx_raw    = (const int*)d_in[1];
    const float* edge_attr = (const float*)d_in[2];
    const float* edge_sh   = (const float*)d_in[3];
    const float* fc_w1     = (const float*)d_in[4];
    const float* fc_b1     = (const float*)d_in[5];
    const float* fc_w2     = (const float*)d_in[6];
    const float* fc_b2     = (const float*)d_in[7];
    const float* bn_weight = (const float*)d_in[8];
    const float* bn_bias   = (const float*)d_in[9];
    float* out = (float*)d_out;

    cudaFuncSetAttribute(k_tp, cudaFuncAttributeMaxDynamicSharedMemorySize,
                         (int)sizeof(SmemT));

    k_detect_idx<<<1, 256>>>(eidx_raw);
    k_convert_idx<<<(NEDGES + 255) / 256, 256>>>(eidx_raw);
    k_transpose_w2<<<dim3(WNUM / 32, NEF / 32), dim3(32, 8)>>>(fc_w2);
    k_prep_bf<<<(NCHUNKS * BFRAG_PER_CHUNK + 255) / 256, 256>>>(fc_b2);
    k_stage_a<<<NEDGES / 64, 256>>>(edge_attr, fc_w1, fc_b1);
    k_init_accum<<<(NNODES * 96 + 255) / 256, 256>>>(node_attr);
    k_tp<<<NEDGES / 128, 256, sizeof(SmemT)>>>(node_attr, edge_sh);
    k_stats<<<NSC + NVC, 256>>>(bn_weight);
    k_final<<<(NNODES * 96 + 255) / 256, 256>>>(bn_bias, out);
}

// round 7
// speedup vs baseline: 8.7402x; 1.3169x over previous
#include <cuda_runtime.h>
#include <cuda_fp16.h>
#include <stdint.h>

#define NNODES 4096
#define NEDGES 32768
#define NSC 48
#define NVC 16
#define NEF 128
#define WNUM 4096
#define BN_EPS 1e-5f
#define INV_SQRT3 0.57735026918962576f
#define ALPHA 0.125f

#define NCHUNKS 64
#define KSTEPS 9                              // 8 data ksteps (K=16) + 1 bias kstep
#define BFRAG_PER_CHUNK (KSTEPS * 8 * 32)     // uint2 entries = 2304
#define BFRAG_BYTES (BFRAG_PER_CHUNK * 8)     // 18432

// ---------------- static device scratch ----------------
__device__ __half g_H[NEDGES * NEF];               // H = relu(ea @ W1 + b1), fp16
__device__ float g_W2p[WNUM * NEF];                // fc_w2 transposed [j][kk]
__device__ __align__(16) uint2 g_Bfrag[NCHUNKS * BFRAG_PER_CHUNK];  // fp16 fragment images
__device__ float g_accum[NNODES * 96];
__device__ float g_mean[NSC];
__device__ float g_rs[NSC];
__device__ float g_rsv[NVC];
__device__ int g_src[NEDGES];
__device__ int g_dst[NEDGES];
__device__ int g_mode;

// ================= helpers =================
__device__ __forceinline__ uint32_t smem_u32(const void* p) {
    uint32_t a;
    asm("{ .reg .u64 t; cvta.to.shared.u64 t, %1; cvt.u32.u64 %0, t; }" : "=r"(a) : "l"(p));
    return a;
}
__device__ __forceinline__ void mma16(float* d, const uint32_t* a, uint32_t b0, uint32_t b1) {
    asm volatile(
        "mma.sync.aligned.m16n8k16.row.col.f32.f16.f16.f32 "
        "{%0,%1,%2,%3}, {%4,%5,%6,%7}, {%8,%9}, {%0,%1,%2,%3};\n"
        : "+f"(d[0]), "+f"(d[1]), "+f"(d[2]), "+f"(d[3])
        : "r"(a[0]), "r"(a[1]), "r"(a[2]), "r"(a[3]), "r"(b0), "r"(b1));
}
__device__ __forceinline__ void cpa16(uint32_t s, const void* g) {
    asm volatile("cp.async.ca.shared.global [%0], [%1], 16;" :: "r"(s), "l"(g));
}
#define CP_COMMIT() asm volatile("cp.async.commit_group;" ::: "memory")
#define CP_WAIT0()  asm volatile("cp.async.wait_group 0;" ::: "memory")

__device__ __forceinline__ float dlrelu(float x) { return (fabsf(x) <= 10.f) ? x : 0.01f * x; }

// column permutation: jp (permuted) -> original j of fc_w2
__device__ __forceinline__ int jorig_of(int jp) {
    int chunk = jp >> 6, q = jp & 63;
    if (chunk < 48) {  // scalar output k = chunk
        return (q < 48) ? q * 48 + chunk : 2304 + (q - 48) * 48 + chunk;
    }
    int k = chunk - 48;  // vector output k
    return (q < 48) ? 3072 + q * 16 + k : 3840 + (q - 48) * 16 + k;
}

// ================= small prep kernels =================
__global__ void k_detect_idx(const int* __restrict__ raw) {
    __shared__ int flag;
    int t = threadIdx.x;
    if (t == 0) flag = 0;
    __syncthreads();
    for (int i = t; i < 2048; i += 256)
        if (raw[2 * i + 1] != 0) flag = 1;
    __syncthreads();
    if (t == 0) g_mode = flag;
}
__global__ void k_convert_idx(const int* __restrict__ raw) {
    int e = blockIdx.x * 256 + threadIdx.x;
    if (e >= NEDGES) return;
    if (g_mode) { g_src[e] = raw[e]; g_dst[e] = raw[NEDGES + e]; }
    else        { g_src[e] = raw[2 * e]; g_dst[e] = raw[2 * (NEDGES + e)]; }
}
__global__ void k_transpose_w2(const float* __restrict__ w2) {
    __shared__ float tile[32][33];
    int j0 = blockIdx.x * 32, k0 = blockIdx.y * 32;
    int tx = threadIdx.x, ty = threadIdx.y;
#pragma unroll
    for (int r = ty; r < 32; r += 8)
        tile[r][tx] = w2[(size_t)(k0 + r) * WNUM + j0 + tx];
    __syncthreads();
#pragma unroll
    for (int r = ty; r < 32; r += 8)
        g_W2p[(size_t)(j0 + r) * NEF + k0 + tx] = tile[tx][r];
}
// build fp16 B fragment images: [chunk][kstep][n8][lane] -> {b0,b1}
__global__ void k_prep_bf(const float* __restrict__ b2) {
    int idx = blockIdx.x * 256 + threadIdx.x;
    if (idx >= NCHUNKS * BFRAG_PER_CHUNK) return;
    int lane = idx & 31;
    int g8 = (idx >> 5) & 7;
    int rest = idx >> 8;        // chunk*9 + s
    int s = rest % KSTEPS, chunk = rest / KSTEPS;
    int q = g8 * 8 + (lane >> 2);
    int jo = jorig_of(chunk * 64 + q);
    int k0 = s * 16 + (lane & 3) * 2;
    float f[4];
#pragma unroll
    for (int r = 0; r < 4; ++r) {
        int k = k0 + (r >> 1) * 8 + (r & 1);
        f[r] = (k < 128) ? g_W2p[jo * 128 + k] : ((k == 128) ? b2[jo] : 0.f);
    }
    uint2 out;
    __half2 h0 = __floats2half2_rn(f[0], f[1]);
    __half2 h1 = __floats2half2_rn(f[2], f[3]);
    out.x = *reinterpret_cast<uint32_t*>(&h0);
    out.y = *reinterpret_cast<uint32_t*>(&h1);
    g_Bfrag[idx] = out;
}

// ---------------- Stage A: H = relu(ea @ W1 + b1) -> fp16 ----------------
__global__ __launch_bounds__(256) void k_stage_a(const float* __restrict__ ea,
                                                 const float* __restrict__ w1,
                                                 const float* __restrict__ b1) {
    __shared__ float As[32][65];
    __shared__ float Ws[32][128];
    int t = threadIdx.x;
    int tx = t & 31, ty = t >> 5;
    int e0 = blockIdx.x * 64;
    float acc[8][4];
#pragma unroll
    for (int i = 0; i < 8; ++i)
#pragma unroll
        for (int j = 0; j < 4; ++j) acc[i][j] = 0.f;

    for (int k0 = 0; k0 < NEF; k0 += 32) {
        for (int idx = t; idx < 64 * 32; idx += 256) {
            int e = idx >> 5, kk = idx & 31;
            As[kk][e] = ea[(size_t)(e0 + e) * NEF + k0 + kk];
        }
        for (int idx = t; idx < 32 * 128; idx += 256) {
            int kk = idx >> 7, cc = idx & 127;
            Ws[kk][cc] = w1[(size_t)(k0 + kk) * NEF + cc];
        }
        __syncthreads();
#pragma unroll 8
        for (int kk = 0; kk < 32; ++kk) {
            float4 b = *reinterpret_cast<const float4*>(&Ws[kk][tx * 4]);
#pragma unroll
            for (int i = 0; i < 8; ++i) {
                float a = As[kk][ty * 8 + i];
                acc[i][0] = fmaf(a, b.x, acc[i][0]);
                acc[i][1] = fmaf(a, b.y, acc[i][1]);
                acc[i][2] = fmaf(a, b.z, acc[i][2]);
                acc[i][3] = fmaf(a, b.w, acc[i][3]);
            }
        }
        __syncthreads();
    }
    float4 bias = *reinterpret_cast<const float4*>(&b1[tx * 4]);
#pragma unroll
    for (int i = 0; i < 8; ++i) {
        float o0 = fmaxf(acc[i][0] + bias.x, 0.f);
        float o1 = fmaxf(acc[i][1] + bias.y, 0.f);
        float o2 = fmaxf(acc[i][2] + bias.z, 0.f);
        float o3 = fmaxf(acc[i][3] + bias.w, 0.f);
        __half2 h0 = __floats2half2_rn(o0, o1);
        __half2 h1 = __floats2half2_rn(o2, o3);
        uint2 st;
        st.x = *reinterpret_cast<uint32_t*>(&h0);
        st.y = *reinterpret_cast<uint32_t*>(&h1);
        *reinterpret_cast<uint2*>(&g_H[(size_t)(e0 + ty * 8 + i) * NEF + tx * 4]) = st;
    }
}

__global__ void k_init_accum(const float* __restrict__ na) {
    int idx = blockIdx.x * 256 + threadIdx.x;
    if (idx < NNODES * 96) g_accum[idx] = na[idx];
}

// ================= fused fp16 mma.sync GEMM + tensor product + scatter =================
struct SmemT {
    uint2 B[2][BFRAG_PER_CHUNK];   // 2 x 18432 B
    float xs[64][49];
    float xv[64][49];
    float dotv[64][17];
    float sss[64];
    float sv[64][3];
    int dst[64];
};

extern __shared__ __align__(16) char smemraw[];

__global__ __launch_bounds__(128, 3) void k_tp(const float* __restrict__ na,
                                               const float* __restrict__ sh) {
    SmemT& sm = *reinterpret_cast<SmemT*>(smemraw);
    int t = threadIdx.x, lane = t & 31, w = t >> 5;
    int h = w & 1;                 // n-half (4 of 8 n8-groups)
    int mb = (w >> 1) * 32;        // m-block base (32 edges)
    int ebase = blockIdx.x * 64;

    // issue cp.async for chunk 0 -> buf 0
    {
        uint32_t sB = smem_u32(&sm.B[0][0]);
        const char* g = (const char*)g_Bfrag;
#pragma unroll
        for (int i = 0; i < 9; ++i) cpa16(sB + (t + 128 * i) * 16, g + (t + 128 * i) * 16);
        CP_COMMIT();
    }

    // per-edge setup (threads 0..63)
    if (t < 64) {
        int e = ebase + t;
        sm.dst[t] = g_dst[e];
        float4 shv = __ldg(reinterpret_cast<const float4*>(sh) + e);
        sm.sss[t] = shv.x;
        sm.sv[t][0] = shv.y; sm.sv[t][1] = shv.z; sm.sv[t][2] = shv.w;
        const float4* nr = reinterpret_cast<const float4*>(na + (size_t)g_src[e] * 96);
#pragma unroll
        for (int q = 0; q < 24; ++q) {
            float4 v = __ldg(nr + q);
            float vv[4] = {v.x, v.y, v.z, v.w};
#pragma unroll
            for (int j = 0; j < 4; ++j) {
                int c = q * 4 + j;
                if (c < 48) sm.xs[t][c] = vv[j];
                else sm.xv[t][c - 48] = vv[j];
            }
        }
#pragma unroll
        for (int i = 0; i < 16; ++i)
            sm.dotv[t][i] = INV_SQRT3 * (sm.xv[t][3 * i + 0] * shv.y +
                                         sm.xv[t][3 * i + 1] * shv.z +
                                         sm.xv[t][3 * i + 2] * shv.w);
    }

    // load A fragments (fp16) into registers; reused across all 64 chunks
    uint32_t a[2][KSTEPS][4];
    int e0 = ebase + mb + (lane >> 2);
#pragma unroll
    for (int mt = 0; mt < 2; ++mt) {
        const __half* p0 = g_H + (size_t)(e0 + mt * 16) * NEF;
        const __half* p1 = p0 + 8 * NEF;
#pragma unroll
        for (int s = 0; s < 8; ++s) {
            int k0 = s * 16 + (lane & 3) * 2;
            a[mt][s][0] = *reinterpret_cast<const uint32_t*>(p0 + k0);
            a[mt][s][1] = *reinterpret_cast<const uint32_t*>(p1 + k0);
            a[mt][s][2] = *reinterpret_cast<const uint32_t*>(p0 + k0 + 8);
            a[mt][s][3] = *reinterpret_cast<const uint32_t*>(p1 + k0 + 8);
        }
        uint32_t one = ((lane & 3) == 0) ? 0x00003c00u : 0u;  // half2(1,0)
        a[mt][8][0] = one; a[mt][8][1] = one;
        a[mt][8][2] = 0u;  a[mt][8][3] = 0u;
    }

#pragma unroll 1
    for (int c = 0; c < NCHUNKS; ++c) {
        int p = c & 1;
        CP_WAIT0();
        __syncthreads();
        // prefetch next chunk into other buffer
        if (c + 1 < NCHUNKS) {
            uint32_t sB = smem_u32(&sm.B[1 - p][0]);
            const char* g = (const char*)(g_Bfrag + (size_t)(c + 1) * BFRAG_PER_CHUNK);
#pragma unroll
            for (int i = 0; i < 9; ++i) cpa16(sB + (t + 128 * i) * 16, g + (t + 128 * i) * 16);
            CP_COMMIT();
        }
        // ---- MMA: m32 x n32 per warp, K=144 (128 data + bias) ----
        float acc[2][4][4];
#pragma unroll
        for (int mt = 0; mt < 2; ++mt)
#pragma unroll
            for (int b = 0; b < 4; ++b)
#pragma unroll
                for (int r = 0; r < 4; ++r) acc[mt][b][r] = 0.f;
#pragma unroll
        for (int s = 0; s < KSTEPS; ++s) {
#pragma unroll
            for (int b = 0; b < 4; ++b) {
                uint2 bf = sm.B[p][(s * 8 + h * 4 + b) * 32 + lane];
                mma16(acc[0][b], a[0][s], bf.x, bf.y);
                mma16(acc[1][b], a[1][s], bf.x, bf.y);
            }
        }
        // ---- epilogue ----
        if (c < 48) {
            float pxs[2][2] = {{0.f, 0.f}, {0.f, 0.f}};
            float pdot[2][2] = {{0.f, 0.f}, {0.f, 0.f}};
#pragma unroll
            for (int mt = 0; mt < 2; ++mt) {
                int el0 = mb + mt * 16 + (lane >> 2);
#pragma unroll
                for (int b = 0; b < 4; ++b) {
                    int g8 = h * 4 + b;
                    int q0 = g8 * 8 + (lane & 3) * 2;
                    float w00 = dlrelu(acc[mt][b][0]), w01 = dlrelu(acc[mt][b][1]);
                    float w10 = dlrelu(acc[mt][b][2]), w11 = dlrelu(acc[mt][b][3]);
                    if (g8 < 6) {
                        pxs[mt][0] += sm.xs[el0][q0] * w00 + sm.xs[el0][q0 + 1] * w01;
                        pxs[mt][1] += sm.xs[el0 + 8][q0] * w10 + sm.xs[el0 + 8][q0 + 1] * w11;
                    } else {
                        int i0 = q0 - 48;
                        pdot[mt][0] += sm.dotv[el0][i0] * w00 + sm.dotv[el0][i0 + 1] * w01;
                        pdot[mt][1] += sm.dotv[el0 + 8][i0] * w10 + sm.dotv[el0 + 8][i0 + 1] * w11;
                    }
                }
            }
#pragma unroll
            for (int mt = 0; mt < 2; ++mt)
#pragma unroll
                for (int rh = 0; rh < 2; ++rh) {
                    float v = pxs[mt][rh];
                    v += __shfl_xor_sync(0xffffffffu, v, 1);
                    v += __shfl_xor_sync(0xffffffffu, v, 2);
                    pxs[mt][rh] = v;
                    float u = pdot[mt][rh];
                    u += __shfl_xor_sync(0xffffffffu, u, 1);
                    u += __shfl_xor_sync(0xffffffffu, u, 2);
                    pdot[mt][rh] = u;
                }
            int j = lane & 3;
            float xsj = (j == 0) ? pxs[0][0] : (j == 1) ? pxs[0][1]
                      : (j == 2) ? pxs[1][0] : pxs[1][1];
            float dtj = (j == 0) ? pdot[0][0] : (j == 1) ? pdot[0][1]
                      : (j == 2) ? pdot[1][0] : pdot[1][1];
            int el = mb + (j >> 1) * 16 + (j & 1) * 8 + (lane >> 2);
            float out = fmaf(sm.sss[el], xsj, dtj);
            atomicAdd(g_accum + (size_t)sm.dst[el] * 96 + c, ALPHA * out);
        } else {
            int kk = c - 48;
            float t1[2][2] = {{0.f, 0.f}, {0.f, 0.f}};
            float tv[2][2][3];
#pragma unroll
            for (int mt = 0; mt < 2; ++mt)
#pragma unroll
                for (int rh = 0; rh < 2; ++rh)
#pragma unroll
                    for (int m = 0; m < 3; ++m) tv[mt][rh][m] = 0.f;
#pragma unroll
            for (int mt = 0; mt < 2; ++mt) {
                int el0 = mb + mt * 16 + (lane >> 2);
#pragma unroll
                for (int b = 0; b < 4; ++b) {
                    int g8 = h * 4 + b;
                    int q0 = g8 * 8 + (lane & 3) * 2;
                    float w00 = dlrelu(acc[mt][b][0]), w01 = dlrelu(acc[mt][b][1]);
                    float w10 = dlrelu(acc[mt][b][2]), w11 = dlrelu(acc[mt][b][3]);
                    if (g8 < 6) {
                        t1[mt][0] += sm.xs[el0][q0] * w00 + sm.xs[el0][q0 + 1] * w01;
                        t1[mt][1] += sm.xs[el0 + 8][q0] * w10 + sm.xs[el0 + 8][q0 + 1] * w11;
                    } else {
                        int i0 = q0 - 48;
#pragma unroll
                        for (int m = 0; m < 3; ++m) {
                            tv[mt][0][m] += sm.xv[el0][3 * i0 + m] * w00 +
                                            sm.xv[el0][3 * (i0 + 1) + m] * w01;
                            tv[mt][1][m] += sm.xv[el0 + 8][3 * i0 + m] * w10 +
                                            sm.xv[el0 + 8][3 * (i0 + 1) + m] * w11;
                        }
                    }
                }
            }
#pragma unroll
            for (int mt = 0; mt < 2; ++mt)
#pragma unroll
                for (int rh = 0; rh < 2; ++rh) {
                    float v = t1[mt][rh];
                    v += __shfl_xor_sync(0xffffffffu, v, 1);
                    v += __shfl_xor_sync(0xffffffffu, v, 2);
                    t1[mt][rh] = v;
#pragma unroll
                    for (int m = 0; m < 3; ++m) {
                        float u = tv[mt][rh][m];
                        u += __shfl_xor_sync(0xffffffffu, u, 1);
                        u += __shfl_xor_sync(0xffffffffu, u, 2);
                        tv[mt][rh][m] = u;
                    }
                }
            int j = lane & 3;
            float t1j = (j == 0) ? t1[0][0] : (j == 1) ? t1[0][1]
                      : (j == 2) ? t1[1][0] : t1[1][1];
            float tvj[3];
#pragma unroll
            for (int m = 0; m < 3; ++m)
                tvj[m] = (j == 0) ? tv[0][0][m] : (j == 1) ? tv[0][1][m]
                       : (j == 2) ? tv[1][0][m] : tv[1][1][m];
            int el = mb + (j >> 1) * 16 + (j & 1) * 8 + (lane >> 2);
            float ssv = sm.sss[el];
            float* base = g_accum + (size_t)sm.dst[el] * 96 + 48 + 3 * kk;
#pragma unroll
            for (int m = 0; m < 3; ++m)
                atomicAdd(base + m, ALPHA * fmaf(t1j, sm.sv[el][m], ssv * tvj[m]));
        }
    }
}

// ---------------- batchnorm statistics ----------------
__global__ __launch_bounds__(256) void k_stats(const float* __restrict__ bnw) {
    __shared__ float r1[256], r2[256];
    int b = blockIdx.x, t = threadIdx.x;
    float s1 = 0.f, s2 = 0.f;
    if (b < NSC) {
        for (int n = t; n < NNODES; n += 256) {
            float x = g_accum[(size_t)n * 96 + b];
            s1 += x;
            s2 += x * x;
        }
    } else {
        int k = b - NSC;
        for (int n = t; n < NNODES; n += 256) {
            const float* p = &g_accum[(size_t)n * 96 + 48 + 3 * k];
            s2 += p[0] * p[0] + p[1] * p[1] + p[2] * p[2];
        }
    }
    r1[t] = s1;
    r2[t] = s2;
    __syncthreads();
    for (int off = 128; off > 0; off >>= 1) {
        if (t < off) { r1[t] += r1[t + off]; r2[t] += r2[t + off]; }
        __syncthreads();
    }
    if (t == 0) {
        if (b < NSC) {
            float mean = r1[0] / (float)NNODES;
            float var = r2[0] / (float)NNODES - mean * mean;
            g_mean[b] = mean;
            g_rs[b] = rsqrtf(var + BN_EPS) * bnw[b];
        } else {
            int k = b - NSC;
            float vn = r2[0] / (3.0f * (float)NNODES);
            g_rsv[k] = rsqrtf(vn + BN_EPS) * bnw[NSC + k];
        }
    }
}

__global__ void k_final(const float* __restrict__ bnb, float* __restrict__ out) {
    int idx = blockIdx.x * 256 + threadIdx.x;
    if (idx >= NNODES * 96) return;
    int c = idx % 96;
    float x = g_accum[idx];
    float o;
    if (c < NSC) o = (x - g_mean[c]) * g_rs[c] + bnb[c];
    else         o = x * g_rsv[(c - 48) / 3];
    out[idx] = o;
}

// ---------------- launch ----------------
extern "C" void kernel_launch(void* const* d_in, const int* in_sizes, int n_in,
                              void* d_out, int out_size) {
    const float* node_attr = (const float*)d_in[0];
    const int* eidx_raw    = (const int*)d_in[1];
    const float* edge_attr = (const float*)d_in[2];
    const float* edge_sh   = (const float*)d_in[3];
    const float* fc_w1     = (const float*)d_in[4];
    const float* fc_b1     = (const float*)d_in[5];
    const float* fc_w2     = (const float*)d_in[6];
    const float* fc_b2     = (const float*)d_in[7];
    const float* bn_weight = (const float*)d_in[8];
    const float* bn_bias   = (const float*)d_in[9];
    float* out = (float*)d_out;

    cudaFuncSetAttribute(k_tp, cudaFuncAttributeMaxDynamicSharedMemorySize,
                         (int)sizeof(SmemT));

    k_detect_idx<<<1, 256>>>(eidx_raw);
    k_convert_idx<<<(NEDGES + 255) / 256, 256>>>(eidx_raw);
    k_transpose_w2<<<dim3(WNUM / 32, NEF / 32), dim3(32, 8)>>>(fc_w2);
    k_prep_bf<<<(NCHUNKS * BFRAG_PER_CHUNK + 255) / 256, 256>>>(fc_b2);
    k_stage_a<<<NEDGES / 64, 256>>>(edge_attr, fc_w1, fc_b1);
    k_init_accum<<<(NNODES * 96 + 255) / 256, 256>>>(node_attr);
    k_tp<<<NEDGES / 64, 128, sizeof(SmemT)>>>(node_attr, edge_sh);
    k_stats<<<NSC + NVC, 256>>>(bn_weight);
    k_final<<<(NNODES * 96 + 255) / 256, 256>>>(bn_bias, out);
}

// round 9
// speedup vs baseline: 9.6666x; 1.1060x over previous
#include <cuda_runtime.h>
#include <cuda_fp16.h>
#include <stdint.h>

#define NNODES 4096
#define NEDGES 32768
#define NSC 48
#define NVC 16
#define NEF 128
#define WNUM 4096
#define BN_EPS 1e-5f
#define INV_SQRT3 0.57735026918962576f
#define ALPHA 0.125f

#define NCHUNKS 64
#define KSTEPS 9                              // 8 data ksteps (K=16) + 1 bias kstep
#define BFRAG_PER_CHUNK (KSTEPS * 8 * 32)     // uint2 entries = 2304
#define NBF_TOTAL (NCHUNKS * BFRAG_PER_CHUNK) // 147456
#define NW1F 4608                             // 9 ksteps * 16 n8 * 32 lanes

// ---------------- static device scratch ----------------
__device__ float g_W2p[WNUM * NEF];                // fc_w2 transposed [j][kk]
__device__ __align__(16) uint2 g_Bfrag[NBF_TOTAL]; // fp16 W2 fragment images
__device__ __align__(16) uint2 g_W1frag[NW1F];     // fp16 W1+b1 fragment images
__device__ float g_accum[NNODES * 96];
__device__ float g_mean[NSC];
__device__ float g_rs[NSC];
__device__ float g_rsv[NVC];
__device__ int g_src[NEDGES];
__device__ int g_dst[NEDGES];
__device__ int g_mode;

// ================= helpers =================
__device__ __forceinline__ uint32_t smem_u32(const void* p) {
    uint32_t a;
    asm("{ .reg .u64 t; cvta.to.shared.u64 t, %1; cvt.u32.u64 %0, t; }" : "=r"(a) : "l"(p));
    return a;
}
__device__ __forceinline__ void mma16(float* d, const uint32_t* a, uint32_t b0, uint32_t b1) {
    asm volatile(
        "mma.sync.aligned.m16n8k16.row.col.f32.f16.f16.f32 "
        "{%0,%1,%2,%3}, {%4,%5,%6,%7}, {%8,%9}, {%0,%1,%2,%3};\n"
        : "+f"(d[0]), "+f"(d[1]), "+f"(d[2]), "+f"(d[3])
        : "r"(a[0]), "r"(a[1]), "r"(a[2]), "r"(a[3]), "r"(b0), "r"(b1));
}
__device__ __forceinline__ void cpa16(uint32_t s, const void* g) {
    asm volatile("cp.async.ca.shared.global [%0], [%1], 16;" :: "r"(s), "l"(g));
}
#define CP_COMMIT() asm volatile("cp.async.commit_group;" ::: "memory")
#define CP_WAIT0()  asm volatile("cp.async.wait_group 0;" ::: "memory")

__device__ __forceinline__ float dlrelu(float x) { return (fabsf(x) <= 10.f) ? x : 0.01f * x; }
__device__ __forceinline__ uint32_t pack_relu(float a, float b) {
    __half2 h = __floats2half2_rn(fmaxf(a, 0.f), fmaxf(b, 0.f));
    return *reinterpret_cast<uint32_t*>(&h);
}

// column permutation: jp (permuted) -> original j of fc_w2
__device__ __forceinline__ int jorig_of(int jp) {
    int chunk = jp >> 6, q = jp & 63;
    if (chunk < 48) {
        return (q < 48) ? q * 48 + chunk : 2304 + (q - 48) * 48 + chunk;
    }
    int k = chunk - 48;
    return (q < 48) ? 3072 + q * 16 + k : 3840 + (q - 48) * 16 + k;
}

// ================= small prep kernels =================
__global__ void k_detect_idx(const int* __restrict__ raw) {
    __shared__ int flag;
    int t = threadIdx.x;
    if (t == 0) flag = 0;
    __syncthreads();
    for (int i = t; i < 2048; i += 256)
        if (raw[2 * i + 1] != 0) flag = 1;
    __syncthreads();
    if (t == 0) g_mode = flag;
}
// idx convert + accumulator init (merged)
__global__ void k_misc(const int* __restrict__ raw, const float* __restrict__ na) {
    int idx = blockIdx.x * 256 + threadIdx.x;
    if (idx < NEDGES) {
        if (g_mode) { g_src[idx] = raw[idx]; g_dst[idx] = raw[NEDGES + idx]; }
        else        { g_src[idx] = raw[2 * idx]; g_dst[idx] = raw[2 * (NEDGES + idx)]; }
    }
    if (idx < NNODES * 96) g_accum[idx] = na[idx];
}
__global__ void k_transpose_w2(const float* __restrict__ w2) {
    __shared__ float tile[32][33];
    int j0 = blockIdx.x * 32, k0 = blockIdx.y * 32;
    int tx = threadIdx.x, ty = threadIdx.y;
#pragma unroll
    for (int r = ty; r < 32; r += 8)
        tile[r][tx] = w2[(size_t)(k0 + r) * WNUM + j0 + tx];
    __syncthreads();
#pragma unroll
    for (int r = ty; r < 32; r += 8)
        g_W2p[(size_t)(j0 + r) * NEF + k0 + tx] = tile[tx][r];
}
// build fp16 fragment images for W2 (permuted) and W1(+biases)
__global__ void k_prep_frags(const float* __restrict__ b2,
                             const float* __restrict__ w1,
                             const float* __restrict__ b1) {
    int idx = blockIdx.x * 256 + threadIdx.x;
    if (idx < NBF_TOTAL) {
        int lane = idx & 31;
        int g8 = (idx >> 5) & 7;
        int rest = idx >> 8;        // chunk*9 + s
        int s = rest % KSTEPS, chunk = rest / KSTEPS;
        int q = g8 * 8 + (lane >> 2);
        int jo = jorig_of(chunk * 64 + q);
        int k0 = s * 16 + (lane & 3) * 2;
        float f[4];
#pragma unroll
        for (int r = 0; r < 4; ++r) {
            int k = k0 + (r >> 1) * 8 + (r & 1);
            f[r] = (k < 128) ? g_W2p[jo * 128 + k] : ((k == 128) ? b2[jo] : 0.f);
        }
        uint2 out;
        __half2 h0 = __floats2half2_rn(f[0], f[1]);
        __half2 h1 = __floats2half2_rn(f[2], f[3]);
        out.x = *reinterpret_cast<uint32_t*>(&h0);
        out.y = *reinterpret_cast<uint32_t*>(&h1);
        g_Bfrag[idx] = out;
    } else if (idx < NBF_TOTAL + NW1F) {
        int v = idx - NBF_TOTAL;
        int lane = v & 31;
        int g = (v >> 5) & 15;
        int s = v >> 9;             // 0..8
        int col = g * 8 + (lane >> 2);
        int k0 = s * 16 + (lane & 3) * 2;
        float f[4];
#pragma unroll
        for (int r = 0; r < 4; ++r) {
            int k = k0 + (r >> 1) * 8 + (r & 1);
            f[r] = (k < 128) ? w1[k * 128 + col] : ((k == 128) ? b1[col] : 0.f);
        }
        uint2 out;
        __half2 h0 = __floats2half2_rn(f[0], f[1]);
        __half2 h1 = __floats2half2_rn(f[2], f[3]);
        out.x = *reinterpret_cast<uint32_t*>(&h0);
        out.y = *reinterpret_cast<uint32_t*>(&h1);
        g_W1frag[v] = out;
    }
}

// ================= fused stage-A + fp16 mma GEMM + tensor product + scatter =================
struct SmemT {
    uint2 B[2][BFRAG_PER_CHUNK];   // 36864 B — holds W1frag during prologue
    float xs[64][49];              // xs/xv area doubles as ea_h (18432 B) during prologue
    float xv[64][49];
    float dotv[64][17];
    float sss[64];
    float sv[64][3];
    int dst[64];
};

extern __shared__ __align__(16) char smemraw[];

__global__ __launch_bounds__(128, 3) void k_tp(const float* __restrict__ na,
                                               const float* __restrict__ sh,
                                               const float* __restrict__ ea) {
    SmemT& sm = *reinterpret_cast<SmemT*>(smemraw);
    int t = threadIdx.x, lane = t & 31, w = t >> 5;
    int h = w & 1;                 // n-half
    int mb = (w >> 1) * 32;        // m-block base (32 edges)
    int ebase = blockIdx.x * 64;
    int r = lane >> 2, q = lane & 3;

    // ---- 1: stream W1 fragment images into the B double-buffer area ----
    {
        uint32_t sB = smem_u32(&sm.B[0][0]);
        const char* g = (const char*)g_W1frag;
#pragma unroll
        for (int i = 0; i < 18; ++i) cpa16(sB + (t + 128 * i) * 16, g + (t + 128 * i) * 16);
        CP_COMMIT();
    }
    // ---- 2: ea tile -> fp16 permuted smem image (overlaying xs/xv) ----
    __half* eah = reinterpret_cast<__half*>(&sm.xs[0][0]);
    for (int i = t; i < 64 * 64; i += 128) {
        int e = i >> 6, c = (i & 63) * 2;
        float2 v = *reinterpret_cast<const float2*>(ea + (size_t)(ebase + e) * 128 + c);
        int s = c >> 4, ww = c & 15;
        int pos = ((ww & 7) >> 1) * 4 + ((ww >> 3) << 1);
        __half2 hp = __floats2half2_rn(v.x, v.y);
        *reinterpret_cast<__half2*>(eah + e * 144 + s * 16 + pos) = hp;
    }
    CP_WAIT0();
    __syncthreads();

    // ---- 3: prologue MMA — compute H fragments (A frags for main loop) ----
    uint32_t afr[2][KSTEPS][4];
    uint32_t one = (q == 0) ? 0x00003c00u : 0u;   // half2(1, 0)
    const uint2* w1f = reinterpret_cast<const uint2*>(&sm.B[0][0]);
#pragma unroll
    for (int mt = 0; mt < 2; ++mt) {
        float accH[16][4];
#pragma unroll
        for (int g = 0; g < 16; ++g)
            accH[g][0] = accH[g][1] = accH[g][2] = accH[g][3] = 0.f;
        const __half* row0 = eah + (mb + mt * 16 + r) * 144;
        const __half* row8 = row0 + 8 * 144;
#pragma unroll 1
        for (int s = 0; s < KSTEPS; ++s) {
            uint32_t af[4];
            if (s < 8) {
                uint2 ae0 = *reinterpret_cast<const uint2*>(row0 + s * 16 + q * 4);
                uint2 ae1 = *reinterpret_cast<const uint2*>(row8 + s * 16 + q * 4);
                af[0] = ae0.x; af[1] = ae1.x; af[2] = ae0.y; af[3] = ae1.y;
            } else {
                af[0] = one; af[1] = one; af[2] = 0u; af[3] = 0u;
            }
#pragma unroll
            for (int g = 0; g < 16; ++g) {
                uint2 bf = w1f[(s * 16 + g) * 32 + lane];
                mma16(accH[g], af, bf.x, bf.y);
            }
        }
#pragma unroll
        for (int sp = 0; sp < 8; ++sp) {
            afr[mt][sp][0] = pack_relu(accH[2 * sp][0], accH[2 * sp][1]);
            afr[mt][sp][1] = pack_relu(accH[2 * sp][2], accH[2 * sp][3]);
            afr[mt][sp][2] = pack_relu(accH[2 * sp + 1][0], accH[2 * sp + 1][1]);
            afr[mt][sp][3] = pack_relu(accH[2 * sp + 1][2], accH[2 * sp + 1][3]);
        }
        afr[mt][8][0] = one; afr[mt][8][1] = one; afr[mt][8][2] = 0u; afr[mt][8][3] = 0u;
    }
    __syncthreads();   // all warps done reading W1frag / ea_h

    // ---- 4: start B pipeline (chunk 0 -> buf 0) ----
    {
        uint32_t sB = smem_u32(&sm.B[0][0]);
        const char* g = (const char*)g_Bfrag;
#pragma unroll
        for (int i = 0; i < 9; ++i) cpa16(sB + (t + 128 * i) * 16, g + (t + 128 * i) * 16);
        CP_COMMIT();
    }
    // ---- 5: per-edge node data (overwrites dead ea_h region) ----
    if (t < 64) {
        int e = ebase + t;
        sm.dst[t] = g_dst[e];
        float4 shv = __ldg(reinterpret_cast<const float4*>(sh) + e);
        sm.sss[t] = shv.x;
        sm.sv[t][0] = shv.y; sm.sv[t][1] = shv.z; sm.sv[t][2] = shv.w;
        const float4* nr = reinterpret_cast<const float4*>(na + (size_t)g_src[e] * 96);
#pragma unroll
        for (int qq = 0; qq < 24; ++qq) {
            float4 v = __ldg(nr + qq);
            float vv[4] = {v.x, v.y, v.z, v.w};
#pragma unroll
            for (int j = 0; j < 4; ++j) {
                int c = qq * 4 + j;
                if (c < 48) sm.xs[t][c] = vv[j];
                else sm.xv[t][c - 48] = vv[j];
            }
        }
#pragma unroll
        for (int i = 0; i < 16; ++i)
            sm.dotv[t][i] = INV_SQRT3 * (sm.xv[t][3 * i + 0] * shv.y +
                                         sm.xv[t][3 * i + 1] * shv.z +
                                         sm.xv[t][3 * i + 2] * shv.w);
    }

    // ---- 6: main loop ----
#pragma unroll 1
    for (int c = 0; c < NCHUNKS; ++c) {
        int p = c & 1;
        CP_WAIT0();
        __syncthreads();
        if (c + 1 < NCHUNKS) {
            uint32_t sB = smem_u32(&sm.B[1 - p][0]);
            const char* g = (const char*)(g_Bfrag + (size_t)(c + 1) * BFRAG_PER_CHUNK);
#pragma unroll
            for (int i = 0; i < 9; ++i) cpa16(sB + (t + 128 * i) * 16, g + (t + 128 * i) * 16);
            CP_COMMIT();
        }
        // ---- MMA: m32 x n32 per warp, K=144 ----
        float acc[2][4][4];
#pragma unroll
        for (int mt = 0; mt < 2; ++mt)
#pragma unroll
            for (int b = 0; b < 4; ++b)
#pragma unroll
                for (int rr = 0; rr < 4; ++rr) acc[mt][b][rr] = 0.f;
#pragma unroll
        for (int s = 0; s < KSTEPS; ++s) {
#pragma unroll
            for (int b = 0; b < 4; ++b) {
                uint2 bf = sm.B[p][(s * 8 + h * 4 + b) * 32 + lane];
                mma16(acc[0][b], afr[0][s], bf.x, bf.y);
                mma16(acc[1][b], afr[1][s], bf.x, bf.y);
            }
        }
        // ---- epilogue ----
        if (c < 48) {
            float pxs[2][2] = {{0.f, 0.f}, {0.f, 0.f}};
            float pdot[2][2] = {{0.f, 0.f}, {0.f, 0.f}};
#pragma unroll
            for (int mt = 0; mt < 2; ++mt) {
                int el0 = mb + mt * 16 + r;
#pragma unroll
                for (int b = 0; b < 4; ++b) {
                    int g8 = h * 4 + b;
                    int q0 = g8 * 8 + q * 2;
                    float w00 = dlrelu(acc[mt][b][0]), w01 = dlrelu(acc[mt][b][1]);
                    float w10 = dlrelu(acc[mt][b][2]), w11 = dlrelu(acc[mt][b][3]);
                    if (g8 < 6) {
                        pxs[mt][0] += sm.xs[el0][q0] * w00 + sm.xs[el0][q0 + 1] * w01;
                        pxs[mt][1] += sm.xs[el0 + 8][q0] * w10 + sm.xs[el0 + 8][q0 + 1] * w11;
                    } else {
                        int i0 = q0 - 48;
                        pdot[mt][0] += sm.dotv[el0][i0] * w00 + sm.dotv[el0][i0 + 1] * w01;
                        pdot[mt][1] += sm.dotv[el0 + 8][i0] * w10 + sm.dotv[el0 + 8][i0 + 1] * w11;
                    }
                }
            }
#pragma unroll
            for (int mt = 0; mt < 2; ++mt)
#pragma unroll
                for (int rh = 0; rh < 2; ++rh) {
                    float v = pxs[mt][rh];
                    v += __shfl_xor_sync(0xffffffffu, v, 1);
                    v += __shfl_xor_sync(0xffffffffu, v, 2);
                    pxs[mt][rh] = v;
                    float u = pdot[mt][rh];
                    u += __shfl_xor_sync(0xffffffffu, u, 1);
                    u += __shfl_xor_sync(0xffffffffu, u, 2);
                    pdot[mt][rh] = u;
                }
            int j = lane & 3;
            float xsj = (j == 0) ? pxs[0][0] : (j == 1) ? pxs[0][1]
                      : (j == 2) ? pxs[1][0] : pxs[1][1];
            float dtj = (j == 0) ? pdot[0][0] : (j == 1) ? pdot[0][1]
                      : (j == 2) ? pdot[1][0] : pdot[1][1];
            int el = mb + (j >> 1) * 16 + (j & 1) * 8 + r;
            float out = fmaf(sm.sss[el], xsj, dtj);
            atomicAdd(g_accum + (size_t)sm.dst[el] * 96 + c, ALPHA * out);
        } else {
            int kk = c - 48;
            float t1[2][2] = {{0.f, 0.f}, {0.f, 0.f}};
            float tv[2][2][3];
#pragma unroll
            for (int mt = 0; mt < 2; ++mt)
#pragma unroll
                for (int rh = 0; rh < 2; ++rh)
#pragma unroll
                    for (int m = 0; m < 3; ++m) tv[mt][rh][m] = 0.f;
#pragma unroll
            for (int mt = 0; mt < 2; ++mt) {
                int el0 = mb + mt * 16 + r;
#pragma unroll
                for (int b = 0; b < 4; ++b) {
                    int g8 = h * 4 + b;
                    int q0 = g8 * 8 + q * 2;
                    float w00 = dlrelu(acc[mt][b][0]), w01 = dlrelu(acc[mt][b][1]);
                    float w10 = dlrelu(acc[mt][b][2]), w11 = dlrelu(acc[mt][b][3]);
                    if (g8 < 6) {
                        t1[mt][0] += sm.xs[el0][q0] * w00 + sm.xs[el0][q0 + 1] * w01;
                        t1[mt][1] += sm.xs[el0 + 8][q0] * w10 + sm.xs[el0 + 8][q0 + 1] * w11;
                    } else {
                        int i0 = q0 - 48;
#pragma unroll
                        for (int m = 0; m < 3; ++m) {
                            tv[mt][0][m] += sm.xv[el0][3 * i0 + m] * w00 +
                                            sm.xv[el0][3 * (i0 + 1) + m] * w01;
                            tv[mt][1][m] += sm.xv[el0 + 8][3 * i0 + m] * w10 +
                                            sm.xv[el0 + 8][3 * (i0 + 1) + m] * w11;
                        }
                    }
                }
            }
#pragma unroll
            for (int mt = 0; mt < 2; ++mt)
#pragma unroll
                for (int rh = 0; rh < 2; ++rh) {
                    float v = t1[mt][rh];
                    v += __shfl_xor_sync(0xffffffffu, v, 1);
                    v += __shfl_xor_sync(0xffffffffu, v, 2);
                    t1[mt][rh] = v;
#pragma unroll
                    for (int m = 0; m < 3; ++m) {
                        float u = tv[mt][rh][m];
                        u += __shfl_xor_sync(0xffffffffu, u, 1);
                        u += __shfl_xor_sync(0xffffffffu, u, 2);
                        tv[mt][rh][m] = u;
                    }
                }
            int j = lane & 3;
            float t1j = (j == 0) ? t1[0][0] : (j == 1) ? t1[0][1]
                      : (j == 2) ? t1[1][0] : t1[1][1];
            float tvj[3];
#pragma unroll
            for (int m = 0; m < 3; ++m)
                tvj[m] = (j == 0) ? tv[0][0][m] : (j == 1) ? tv[0][1][m]
                       : (j == 2) ? tv[1][0][m] : tv[1][1][m];
            int el = mb + (j >> 1) * 16 + (j & 1) * 8 + r;
            float ssv = sm.sss[el];
            float* base = g_accum + (size_t)sm.dst[el] * 96 + 48 + 3 * kk;
#pragma unroll
            for (int m = 0; m < 3; ++m)
                atomicAdd(base + m, ALPHA * fmaf(t1j, sm.sv[el][m], ssv * tvj[m]));
        }
    }
}

// ---------------- batchnorm statistics ----------------
__global__ __launch_bounds__(256) void k_stats(const float* __restrict__ bnw) {
    __shared__ float r1[256], r2[256];
    int b = blockIdx.x, t = threadIdx.x;
    float s1 = 0.f, s2 = 0.f;
    if (b < NSC) {
        for (int n = t; n < NNODES; n += 256) {
            float x = g_accum[(size_t)n * 96 + b];
            s1 += x;
            s2 += x * x;
        }
    } else {
        int k = b - NSC;
        for (int n = t; n < NNODES; n += 256) {
            const float* p = &g_accum[(size_t)n * 96 + 48 + 3 * k];
            s2 += p[0] * p[0] + p[1] * p[1] + p[2] * p[2];
        }
    }
    r1[t] = s1;
    r2[t] = s2;
    __syncthreads();
    for (int off = 128; off > 0; off >>= 1) {
        if (t < off) { r1[t] += r1[t + off]; r2[t] += r2[t + off]; }
        __syncthreads();
    }
    if (t == 0) {
        if (b < NSC) {
            float mean = r1[0] / (float)NNODES;
            float var = r2[0] / (float)NNODES - mean * mean;
            g_mean[b] = mean;
            g_rs[b] = rsqrtf(var + BN_EPS) * bnw[b];
        } else {
            int k = b - NSC;
            float vn = r2[0] / (3.0f * (float)NNODES);
            g_rsv[k] = rsqrtf(vn + BN_EPS) * bnw[NSC + k];
        }
    }
}

__global__ void k_final(const float* __restrict__ bnb, float* __restrict__ out) {
    int idx = blockIdx.x * 256 + threadIdx.x;
    if (idx >= NNODES * 96) return;
    int c = idx % 96;
    float x = g_accum[idx];
    float o;
    if (c < NSC) o = (x - g_mean[c]) * g_rs[c] + bnb[c];
    else         o = x * g_rsv[(c - 48) / 3];
    out[idx] = o;
}

// ---------------- launch ----------------
extern "C" void kernel_launch(void* const* d_in, const int* in_sizes, int n_in,
                              void* d_out, int out_size) {
    const float* node_attr = (const float*)d_in[0];
    const int* eidx_raw    = (const int*)d_in[1];
    const float* edge_attr = (const float*)d_in[2];
    const float* edge_sh   = (const float*)d_in[3];
    const float* fc_w1     = (const float*)d_in[4];
    const float* fc_b1     = (const float*)d_in[5];
    const float* fc_w2     = (const float*)d_in[6];
    const float* fc_b2     = (const float*)d_in[7];
    const float* bn_weight = (const float*)d_in[8];
    const float* bn_bias   = (const float*)d_in[9];
    float* out = (float*)d_out;

    cudaFuncSetAttribute(k_tp, cudaFuncAttributeMaxDynamicSharedMemorySize,
                         (int)sizeof(SmemT));

    k_detect_idx<<<1, 256>>>(eidx_raw);
    k_misc<<<(NNODES * 96 + 255) / 256, 256>>>(eidx_raw, node_attr);
    k_transpose_w2<<<dim3(WNUM / 32, NEF / 32), dim3(32, 8)>>>(fc_w2);
    k_prep_frags<<<(NBF_TOTAL + NW1F + 255) / 256, 256>>>(fc_b2, fc_w1, fc_b1);
    k_tp<<<NEDGES / 64, 128, sizeof(SmemT)>>>(node_attr, edge_sh, edge_attr);
    k_stats<<<NSC + NVC, 256>>>(bn_weight);
    k_final<<<(NNODES * 96 + 255) / 256, 256>>>(bn_bias, out);
}